// round 4
// baseline (speedup 1.0000x reference)
#include <cuda_runtime.h>
#include <math.h>

// ---------------------------------------------------------------------------
// GPT block: B=2, S=2048, H=2048, NH=16, HD=128   (all fp32 baseline)
// ---------------------------------------------------------------------------

#define GPT_B  2
#define GPT_S  2048
#define GPT_H  2048
#define GPT_BS 4096            // B*S rows

// Scratch (allocation-free rule: __device__ globals)
__device__ float g_h   [(size_t)GPT_BS * GPT_H];        //  33.5 MB  LN output
__device__ float g_qkv [(size_t)GPT_BS * 3 * GPT_H];    // 100.7 MB  QKV
__device__ float g_attn[(size_t)GPT_BS * GPT_H];        //  33.5 MB  attn out
__device__ float g_xmid[(size_t)GPT_BS * GPT_H];        //  33.5 MB  x + attn proj
__device__ float g_ff1 [(size_t)GPT_BS * 4 * GPT_H];    // 134.2 MB  gelu(ff1)

// ---------------------------------------------------------------------------
// LayerNorm: one block per row of 2048 floats
// ---------------------------------------------------------------------------
__global__ __launch_bounds__(256) void ln_kernel(
    const float* __restrict__ x, const float* __restrict__ gw,
    const float* __restrict__ bw, float* __restrict__ out)
{
    int row = blockIdx.x;
    int tid = threadIdx.x;
    const float4* x4 = reinterpret_cast<const float4*>(x + (size_t)row * GPT_H);
    float4 v0 = x4[tid];
    float4 v1 = x4[tid + 256];
    float sum = v0.x + v0.y + v0.z + v0.w + v1.x + v1.y + v1.z + v1.w;
    float sq  = v0.x*v0.x + v0.y*v0.y + v0.z*v0.z + v0.w*v0.w
              + v1.x*v1.x + v1.y*v1.y + v1.z*v1.z + v1.w*v1.w;
    #pragma unroll
    for (int off = 16; off; off >>= 1) {
        sum += __shfl_xor_sync(0xffffffffu, sum, off);
        sq  += __shfl_xor_sync(0xffffffffu, sq , off);
    }
    __shared__ float ssum[8], ssq[8];
    __shared__ float s_mu, s_r;
    int wid = tid >> 5;
    if ((tid & 31) == 0) { ssum[wid] = sum; ssq[wid] = sq; }
    __syncthreads();
    if (tid == 0) {
        float ts = 0.f, tq = 0.f;
        #pragma unroll
        for (int i = 0; i < 8; i++) { ts += ssum[i]; tq += ssq[i]; }
        float mu  = ts * (1.0f / GPT_H);
        float var = tq * (1.0f / GPT_H) - mu * mu;
        s_mu = mu;
        s_r  = rsqrtf(var + 1e-5f);
    }
    __syncthreads();
    float mu = s_mu, r = s_r;
    const float4* g4 = reinterpret_cast<const float4*>(gw);
    const float4* b4 = reinterpret_cast<const float4*>(bw);
    float4 gg0 = g4[tid], gg1 = g4[tid + 256];
    float4 bb0 = b4[tid], bb1 = b4[tid + 256];
    float4 o0, o1;
    o0.x = (v0.x - mu) * r * gg0.x + bb0.x;
    o0.y = (v0.y - mu) * r * gg0.y + bb0.y;
    o0.z = (v0.z - mu) * r * gg0.z + bb0.z;
    o0.w = (v0.w - mu) * r * gg0.w + bb0.w;
    o1.x = (v1.x - mu) * r * gg1.x + bb1.x;
    o1.y = (v1.y - mu) * r * gg1.y + bb1.y;
    o1.z = (v1.z - mu) * r * gg1.z + bb1.z;
    o1.w = (v1.w - mu) * r * gg1.w + bb1.w;
    float4* out4 = reinterpret_cast<float4*>(out + (size_t)row * GPT_H);
    out4[tid]       = o0;
    out4[tid + 256] = o1;
}

// ---------------------------------------------------------------------------
// SGEMM: C[M,N] = act(A[M,K] @ B[K,N] + bias) (+ residual)
// 128x128 tile, BK=8, 256 threads, 8x8 register micro-tile, double buffered
// ---------------------------------------------------------------------------
__device__ __forceinline__ float gelu_f(float x) {
    float x3 = x * x * x;
    return 0.5f * x * (1.0f + tanhf(0.7978845608028654f * (x + 0.044715f * x3)));
}

template<int ACT, bool RES>
__global__ __launch_bounds__(256) void sgemm(
    const float* __restrict__ A, const float* __restrict__ Bm,
    const float* __restrict__ bias, const float* __restrict__ res,
    float* __restrict__ C, int M, int N, int K)
{
    __shared__ float As[2][8][128];
    __shared__ float Bs[2][8][128];

    int tid = threadIdx.x;
    int tx = tid & 15, ty = tid >> 4;
    int n0 = blockIdx.x * 128;
    int m0 = blockIdx.y * 128;

    int arow = tid >> 1, acol = (tid & 1) * 4;
    int brow = tid >> 5, bcol = (tid & 31) * 4;

    const float* Aptr = A  + (size_t)(m0 + arow) * K + acol;
    const float* Bptr = Bm + (size_t)brow * N + n0 + bcol;

    float acc[8][8];
    #pragma unroll
    for (int i = 0; i < 8; i++)
        #pragma unroll
        for (int j = 0; j < 8; j++) acc[i][j] = 0.f;

    // prologue: tile 0
    float4 a  = *(const float4*)Aptr;
    float4 bv = *(const float4*)Bptr;
    As[0][acol + 0][arow] = a.x;
    As[0][acol + 1][arow] = a.y;
    As[0][acol + 2][arow] = a.z;
    As[0][acol + 3][arow] = a.w;
    *(float4*)&Bs[0][brow][bcol] = bv;
    __syncthreads();

    int nk = K >> 3;
    #pragma unroll 1
    for (int kt = 0; kt < nk; kt++) {
        int buf = kt & 1, nbuf = buf ^ 1;
        if (kt + 1 < nk) {
            a  = *(const float4*)(Aptr + (kt + 1) * 8);
            bv = *(const float4*)(Bptr + (size_t)(kt + 1) * 8 * N);
        }
        #pragma unroll
        for (int kk = 0; kk < 8; kk++) {
            float av[8], bw[8];
            *(float4*)&av[0] = *(const float4*)&As[buf][kk][ty * 8];
            *(float4*)&av[4] = *(const float4*)&As[buf][kk][ty * 8 + 4];
            *(float4*)&bw[0] = *(const float4*)&Bs[buf][kk][tx * 8];
            *(float4*)&bw[4] = *(const float4*)&Bs[buf][kk][tx * 8 + 4];
            #pragma unroll
            for (int i = 0; i < 8; i++)
                #pragma unroll
                for (int j = 0; j < 8; j++)
                    acc[i][j] += av[i] * bw[j];
        }
        if (kt + 1 < nk) {
            As[nbuf][acol + 0][arow] = a.x;
            As[nbuf][acol + 1][arow] = a.y;
            As[nbuf][acol + 2][arow] = a.z;
            As[nbuf][acol + 3][arow] = a.w;
            *(float4*)&Bs[nbuf][brow][bcol] = bv;
        }
        __syncthreads();
    }

    // epilogue
    int crow = m0 + ty * 8;
    int ccol = n0 + tx * 8;
    #pragma unroll
    for (int i = 0; i < 8; i++) {
        size_t off = (size_t)(crow + i) * N + ccol;
        float v[8];
        #pragma unroll
        for (int j = 0; j < 8; j++) {
            float t = acc[i][j] + __ldg(&bias[ccol + j]);
            if (ACT == 1) t = gelu_f(t);
            v[j] = t;
        }
        if (RES) {
            float4 r0 = *(const float4*)(res + off);
            float4 r1 = *(const float4*)(res + off + 4);
            v[0] += r0.x; v[1] += r0.y; v[2] += r0.z; v[3] += r0.w;
            v[4] += r1.x; v[5] += r1.y; v[6] += r1.z; v[7] += r1.w;
        }
        *(float4*)(C + off)     = make_float4(v[0], v[1], v[2], v[3]);
        *(float4*)(C + off + 4) = make_float4(v[4], v[5], v[6], v[7]);
    }
}

// ---------------------------------------------------------------------------
// Flash attention (causal), fp32. Block = one (batch, head, 64-row q-tile).
// Q/K stored d-major (transposed) in smem -> conflict-free float4 reads.
// 256 threads = 16x16; each thread: 4 q-rows x 4 k-cols S-tile, 4x8 O-tile.
// ---------------------------------------------------------------------------
#define ATTN_SMEM_BYTES 114688   // (8192 + 8192 + 8192 + 4096) floats

__global__ __launch_bounds__(256) void attn_kernel(
    const float* __restrict__ qkv, float* __restrict__ attnout)
{
    extern __shared__ float sm[];
    float* Qt = sm;             // [128][64]  d-major
    float* Kt = sm + 8192;      // [128][64]  d-major
    float* Vs = sm + 16384;     // [64][128]  row-major
    float* Ps = sm + 24576;     // [64][64]

    int qt  = blockIdx.x;
    int hh  = blockIdx.y;
    int bb  = blockIdx.z;
    int tid = threadIdx.x;
    int tx = tid & 15, ty = tid >> 4;
    int lrow = tid >> 2, lchunk = tid & 3;   // loader: 64 rows x 4 chunks of 32 d

    const float scale = 0.08838834764831845f;   // 1/sqrt(128)
    const size_t rs = 3 * GPT_H;                // 6144
    const float* qb = qkv + (size_t)bb * GPT_S * rs + hh * 128;
    const float* kb = qb + GPT_H;
    const float* vb = qb + 2 * GPT_H;
    int q0 = qt * 64;

    // load Q tile transposed, pre-scaled
    {
        const float* src = qb + (size_t)(q0 + lrow) * rs + lchunk * 32;
        #pragma unroll
        for (int j = 0; j < 8; j++) {
            float4 v = *(const float4*)(src + j * 4);
            int d = lchunk * 32 + j * 4;
            Qt[(d + 0) * 64 + lrow] = v.x * scale;
            Qt[(d + 1) * 64 + lrow] = v.y * scale;
            Qt[(d + 2) * 64 + lrow] = v.z * scale;
            Qt[(d + 3) * 64 + lrow] = v.w * scale;
        }
    }

    float m_s[4], l_s[4], O[4][8];
    #pragma unroll
    for (int r = 0; r < 4; r++) {
        m_s[r] = -INFINITY; l_s[r] = 0.f;
        #pragma unroll
        for (int j = 0; j < 8; j++) O[r][j] = 0.f;
    }

    #pragma unroll 1
    for (int kt = 0; kt <= qt; kt++) {
        int k0 = kt * 64;
        __syncthreads();   // prior PV done -> safe to overwrite Kt/Vs
        {
            const float* ks = kb + (size_t)(k0 + lrow) * rs + lchunk * 32;
            const float* vsp = vb + (size_t)(k0 + lrow) * rs + lchunk * 32;
            #pragma unroll
            for (int j = 0; j < 8; j++) {
                float4 kv = *(const float4*)(ks + j * 4);
                int d = lchunk * 32 + j * 4;
                Kt[(d + 0) * 64 + lrow] = kv.x;
                Kt[(d + 1) * 64 + lrow] = kv.y;
                Kt[(d + 2) * 64 + lrow] = kv.z;
                Kt[(d + 3) * 64 + lrow] = kv.w;
                float4 vv = *(const float4*)(vsp + j * 4);
                *(float4*)&Vs[lrow * 128 + lchunk * 32 + j * 4] = vv;
            }
        }
        __syncthreads();

        // S = Q K^T  (4x4 per thread)
        float s[4][4];
        #pragma unroll
        for (int r = 0; r < 4; r++)
            #pragma unroll
            for (int c = 0; c < 4; c++) s[r][c] = 0.f;

        #pragma unroll 4
        for (int d = 0; d < 128; d++) {
            float4 qv = *(const float4*)&Qt[d * 64 + ty * 4];
            float4 kv = *(const float4*)&Kt[d * 64 + tx * 4];
            float qa[4] = {qv.x, qv.y, qv.z, qv.w};
            float ka[4] = {kv.x, kv.y, kv.z, kv.w};
            #pragma unroll
            for (int r = 0; r < 4; r++)
                #pragma unroll
                for (int c = 0; c < 4; c++)
                    s[r][c] += qa[r] * ka[c];
        }

        // causal mask (only diagonal tile needs it; q0 == k0 there)
        if (kt == qt) {
            #pragma unroll
            for (int r = 0; r < 4; r++)
                #pragma unroll
                for (int c = 0; c < 4; c++)
                    if (tx * 4 + c > ty * 4 + r) s[r][c] = -INFINITY;
        }

        // online softmax per q-row (16 lanes share a row-group)
        #pragma unroll
        for (int r = 0; r < 4; r++) {
            float mx = fmaxf(fmaxf(s[r][0], s[r][1]), fmaxf(s[r][2], s[r][3]));
            #pragma unroll
            for (int off = 8; off; off >>= 1)
                mx = fmaxf(mx, __shfl_xor_sync(0xffffffffu, mx, off, 16));
            float mnew = fmaxf(m_s[r], mx);
            float p0 = __expf(s[r][0] - mnew);
            float p1 = __expf(s[r][1] - mnew);
            float p2 = __expf(s[r][2] - mnew);
            float p3 = __expf(s[r][3] - mnew);
            float rsum = p0 + p1 + p2 + p3;
            #pragma unroll
            for (int off = 8; off; off >>= 1)
                rsum += __shfl_xor_sync(0xffffffffu, rsum, off, 16);
            float alpha = __expf(m_s[r] - mnew);
            l_s[r] = l_s[r] * alpha + rsum;
            m_s[r] = mnew;
            #pragma unroll
            for (int j = 0; j < 8; j++) O[r][j] *= alpha;
            *(float4*)&Ps[(ty * 4 + r) * 64 + tx * 4] = make_float4(p0, p1, p2, p3);
        }
        __syncthreads();

        // O += P @ V   (cols: tx*4..tx*4+3 and 64+tx*4..64+tx*4+3)
        #pragma unroll 4
        for (int k = 0; k < 64; k++) {
            float4 v0 = *(const float4*)&Vs[k * 128 + tx * 4];
            float4 v1 = *(const float4*)&Vs[k * 128 + 64 + tx * 4];
            #pragma unroll
            for (int r = 0; r < 4; r++) {
                float p = Ps[(ty * 4 + r) * 64 + k];
                O[r][0] += p * v0.x; O[r][1] += p * v0.y;
                O[r][2] += p * v0.z; O[r][3] += p * v0.w;
                O[r][4] += p * v1.x; O[r][5] += p * v1.y;
                O[r][6] += p * v1.z; O[r][7] += p * v1.w;
            }
        }
    }

    // write O / l to attn output [B,S,H] with head offset
    #pragma unroll
    for (int r = 0; r < 4; r++) {
        float inv = 1.0f / l_s[r];
        float* dst = attnout + (size_t)(bb * GPT_S + q0 + ty * 4 + r) * GPT_H + hh * 128;
        *(float4*)(dst + tx * 4) =
            make_float4(O[r][0] * inv, O[r][1] * inv, O[r][2] * inv, O[r][3] * inv);
        *(float4*)(dst + 64 + tx * 4) =
            make_float4(O[r][4] * inv, O[r][5] * inv, O[r][6] * inv, O[r][7] * inv);
    }
}

// ---------------------------------------------------------------------------
// launch
// ---------------------------------------------------------------------------
extern "C" void kernel_launch(void* const* d_in, const int* in_sizes, int n_in,
                              void* d_out, int out_size)
{
    const float* x     = (const float*)d_in[0];
    const float* ln1_g = (const float*)d_in[1];
    const float* ln1_b = (const float*)d_in[2];
    const float* ln2_g = (const float*)d_in[3];
    const float* ln2_b = (const float*)d_in[4];
    const float* w_qkv = (const float*)d_in[5];
    const float* b_qkv = (const float*)d_in[6];
    const float* w_ao  = (const float*)d_in[7];
    const float* b_ao  = (const float*)d_in[8];
    const float* w_ff1 = (const float*)d_in[9];
    const float* b_ff1 = (const float*)d_in[10];
    const float* w_ff2 = (const float*)d_in[11];
    const float* b_ff2 = (const float*)d_in[12];
    float* out = (float*)d_out;

    void* p;
    float *h, *qkv, *attn, *xmid, *ff1;
    cudaGetSymbolAddress(&p, g_h);    h    = (float*)p;
    cudaGetSymbolAddress(&p, g_qkv);  qkv  = (float*)p;
    cudaGetSymbolAddress(&p, g_attn); attn = (float*)p;
    cudaGetSymbolAddress(&p, g_xmid); xmid = (float*)p;
    cudaGetSymbolAddress(&p, g_ff1);  ff1  = (float*)p;

    cudaFuncSetAttribute(attn_kernel,
                         cudaFuncAttributeMaxDynamicSharedMemorySize,
                         ATTN_SMEM_BYTES);

    // 1) LN1
    ln_kernel<<<GPT_BS, 256>>>(x, ln1_g, ln1_b, h);
    // 2) QKV = h @ w_qkv + b_qkv            [4096 x 6144 x 2048]
    sgemm<0, false><<<dim3(48, 32), 256>>>(h, w_qkv, b_qkv, nullptr, qkv,
                                           GPT_BS, 3 * GPT_H, GPT_H);
    // 3) causal flash attention -> attn     [B,S,H]
    attn_kernel<<<dim3(GPT_S / 64, 16, GPT_B), 256, ATTN_SMEM_BYTES>>>(qkv, attn);
    // 4) xmid = x + attn @ w_attn_out + b   [4096 x 2048 x 2048]
    sgemm<0, true><<<dim3(16, 32), 256>>>(attn, w_ao, b_ao, x, xmid,
                                          GPT_BS, GPT_H, GPT_H);
    // 5) LN2
    ln_kernel<<<GPT_BS, 256>>>(xmid, ln2_g, ln2_b, h);
    // 6) ff1 = gelu(h @ w_ff1 + b_ff1)      [4096 x 8192 x 2048]
    sgemm<1, false><<<dim3(64, 32), 256>>>(h, w_ff1, b_ff1, nullptr, ff1,
                                           GPT_BS, 4 * GPT_H, GPT_H);
    // 7) out = xmid + ff1 @ w_ff2 + b_ff2   [4096 x 2048 x 8192]
    sgemm<0, true><<<dim3(16, 32), 256>>>(ff1, w_ff2, b_ff2, xmid, out,
                                          GPT_BS, GPT_H, 4 * GPT_H);
}

// round 8
// speedup vs baseline: 1.9175x; 1.9175x over previous
#include <cuda_runtime.h>
#include <cuda_bf16.h>
#include <stdint.h>
#include <math.h>

// ---------------------------------------------------------------------------
// GPT block on GB300 (compute_103 base ISA):
//   mma.sync bf16x3-split GEMMs + fp32 flash attention
// B=2, S=2048, H=2048, NH=16, HD=128
// ---------------------------------------------------------------------------
#define GPT_B  2
#define GPT_S  2048
#define GPT_H  2048
#define GPT_BS 4096
typedef __nv_bfloat16 bf16;

// ---- scratch (allocation-free rule: __device__ globals) ----
__device__ float g_qkv [(size_t)GPT_BS * 3 * GPT_H];
__device__ float g_xmid[(size_t)GPT_BS * GPT_H];
__device__ bf16  g_h_hi [(size_t)GPT_BS * GPT_H];
__device__ bf16  g_h_lo [(size_t)GPT_BS * GPT_H];
__device__ bf16  g_at_hi[(size_t)GPT_BS * GPT_H];
__device__ bf16  g_at_lo[(size_t)GPT_BS * GPT_H];
__device__ bf16  g_f1_hi[(size_t)GPT_BS * 4 * GPT_H];
__device__ bf16  g_f1_lo[(size_t)GPT_BS * 4 * GPT_H];
// transposed bf16 weights [N,K]
__device__ bf16  g_wqkv_hi[(size_t)3 * GPT_H * GPT_H];
__device__ bf16  g_wqkv_lo[(size_t)3 * GPT_H * GPT_H];
__device__ bf16  g_wao_hi [(size_t)GPT_H * GPT_H];
__device__ bf16  g_wao_lo [(size_t)GPT_H * GPT_H];
__device__ bf16  g_wf1_hi [(size_t)4 * GPT_H * GPT_H];
__device__ bf16  g_wf1_lo [(size_t)4 * GPT_H * GPT_H];
__device__ bf16  g_wf2_hi [(size_t)4 * GPT_H * GPT_H];
__device__ bf16  g_wf2_lo [(size_t)4 * GPT_H * GPT_H];

// ---------------------------------------------------------------------------
// base-ISA PTX helpers (all legal under compute_103)
// ---------------------------------------------------------------------------
__device__ __forceinline__ uint32_t smem_u32(const void* p) {
    uint32_t a;
    asm("{ .reg .u64 t; cvta.to.shared.u64 t, %1; cvt.u32.u64 %0, t; }"
        : "=r"(a) : "l"(p));
    return a;
}
#define CP_ASYNC16(dst, src) \
    asm volatile("cp.async.cg.shared.global [%0], [%1], 16;" \
                 :: "r"(dst), "l"(src))
#define CP_COMMIT() asm volatile("cp.async.commit_group;" ::: "memory")
#define CP_WAIT0()  asm volatile("cp.async.wait_group 0;" ::: "memory")
#define CP_WAIT1()  asm volatile("cp.async.wait_group 1;" ::: "memory")

#define LDMX4(r, addr) \
    asm volatile("ldmatrix.sync.aligned.m8n8.x4.shared.b16 {%0,%1,%2,%3}, [%4];" \
        : "=r"((r)[0]), "=r"((r)[1]), "=r"((r)[2]), "=r"((r)[3]) : "r"(addr))

#define MMA16816(d, a, b0, b1) \
    asm volatile("mma.sync.aligned.m16n8k16.row.col.f32.bf16.bf16.f32 " \
        "{%0,%1,%2,%3}, {%4,%5,%6,%7}, {%8,%9}, {%0,%1,%2,%3};" \
        : "+f"((d)[0]), "+f"((d)[1]), "+f"((d)[2]), "+f"((d)[3]) \
        : "r"((a)[0]), "r"((a)[1]), "r"((a)[2]), "r"((a)[3]), \
          "r"(b0), "r"(b1))

__device__ __forceinline__ void split2(float x, bf16& h, bf16& l) {
    h = __float2bfloat16(x);
    l = __float2bfloat16(x - __bfloat162float(h));
}
__device__ __forceinline__ float gelu_f(float x) {
    float x3 = x * x * x;
    return 0.5f * x * (1.0f + tanhf(0.7978845608028654f * (x + 0.044715f * x3)));
}

// ---------------------------------------------------------------------------
// Weight transpose+split: W[K,N] fp32 -> T_hi/T_lo[N,K] bf16
// ---------------------------------------------------------------------------
__global__ __launch_bounds__(256) void wtrans(
    const float* __restrict__ W, bf16* __restrict__ Th, bf16* __restrict__ Tl,
    int K, int N)
{
    __shared__ float t[32][33];
    int n0 = blockIdx.x * 32, k0 = blockIdx.y * 32;
    int tx = threadIdx.x, ty = threadIdx.y;
    #pragma unroll
    for (int i = 0; i < 32; i += 8)
        t[ty + i][tx] = W[(size_t)(k0 + ty + i) * N + n0 + tx];
    __syncthreads();
    #pragma unroll
    for (int i = 0; i < 32; i += 8) {
        float v = t[tx][ty + i];          // W[k0+tx][n0+ty+i]
        bf16 h, l; split2(v, h, l);
        size_t off = (size_t)(n0 + ty + i) * K + k0 + tx;
        Th[off] = h; Tl[off] = l;
    }
}

// ---------------------------------------------------------------------------
// LayerNorm -> bf16 hi/lo
// ---------------------------------------------------------------------------
__global__ __launch_bounds__(256) void ln_kernel(
    const float* __restrict__ x, const float* __restrict__ gw,
    const float* __restrict__ bw, bf16* __restrict__ oh, bf16* __restrict__ ol)
{
    int row = blockIdx.x, tid = threadIdx.x;
    const float4* x4 = reinterpret_cast<const float4*>(x + (size_t)row * GPT_H);
    float4 v0 = x4[tid], v1 = x4[tid + 256];
    float sum = v0.x + v0.y + v0.z + v0.w + v1.x + v1.y + v1.z + v1.w;
    float sq  = v0.x*v0.x + v0.y*v0.y + v0.z*v0.z + v0.w*v0.w
              + v1.x*v1.x + v1.y*v1.y + v1.z*v1.z + v1.w*v1.w;
    #pragma unroll
    for (int off = 16; off; off >>= 1) {
        sum += __shfl_xor_sync(0xffffffffu, sum, off);
        sq  += __shfl_xor_sync(0xffffffffu, sq , off);
    }
    __shared__ float ssum[8], ssq[8], s_mu, s_r;
    int wid = tid >> 5;
    if ((tid & 31) == 0) { ssum[wid] = sum; ssq[wid] = sq; }
    __syncthreads();
    if (tid == 0) {
        float ts = 0.f, tq = 0.f;
        #pragma unroll
        for (int i = 0; i < 8; i++) { ts += ssum[i]; tq += ssq[i]; }
        float mu = ts * (1.0f / GPT_H);
        s_mu = mu;
        s_r  = rsqrtf(tq * (1.0f / GPT_H) - mu * mu + 1e-5f);
    }
    __syncthreads();
    float mu = s_mu, r = s_r;
    const float4* g4 = reinterpret_cast<const float4*>(gw);
    const float4* b4 = reinterpret_cast<const float4*>(bw);
    float4 gg0 = g4[tid], gg1 = g4[tid + 256];
    float4 bb0 = b4[tid], bb1 = b4[tid + 256];
    float o[8];
    o[0] = (v0.x - mu) * r * gg0.x + bb0.x;
    o[1] = (v0.y - mu) * r * gg0.y + bb0.y;
    o[2] = (v0.z - mu) * r * gg0.z + bb0.z;
    o[3] = (v0.w - mu) * r * gg0.w + bb0.w;
    o[4] = (v1.x - mu) * r * gg1.x + bb1.x;
    o[5] = (v1.y - mu) * r * gg1.y + bb1.y;
    o[6] = (v1.z - mu) * r * gg1.z + bb1.z;
    o[7] = (v1.w - mu) * r * gg1.w + bb1.w;
    size_t base = (size_t)row * GPT_H;
    #pragma unroll
    for (int g = 0; g < 2; g++) {
        int c0 = (g == 0) ? tid * 4 : (tid + 256) * 4;
        #pragma unroll
        for (int p = 0; p < 2; p++) {
            bf16 h0, l0, h1, l1;
            split2(o[g*4 + p*2 + 0], h0, l0);
            split2(o[g*4 + p*2 + 1], h1, l1);
            __nv_bfloat162 hh; hh.x = h0; hh.y = h1;
            __nv_bfloat162 ll; ll.x = l0; ll.y = l1;
            *reinterpret_cast<__nv_bfloat162*>(oh + base + c0 + p*2) = hh;
            *reinterpret_cast<__nv_bfloat162*>(ol + base + c0 + p*2) = ll;
        }
    }
}

// ---------------------------------------------------------------------------
// mma.sync GEMM:  C[M,N] = act(A @ B^T + bias) (+res)
// A: [M,K] bf16 hi/lo,  B: [N,K] bf16 hi/lo (pre-transposed weights)
// 128x128 tile, BK=32, 8 warps (warp tile 64x32), m16n8k16, bf16x3 split.
// Smem rows padded to 40 bf16 (80B) -> ldmatrix conflict-free.
// Stage layout: [Ah | Al | Bh | Bl] x 10240B, 2 stages = 81920B.
// ---------------------------------------------------------------------------
#define GEMM_SMEM 81920

template<int ACT, bool RES, bool BF16OUT>
__global__ __launch_bounds__(256) void gemm_mma(
    const bf16* __restrict__ Ahi, const bf16* __restrict__ Alo,
    const bf16* __restrict__ Bhi, const bf16* __restrict__ Blo,
    const float* __restrict__ bias, const float* __restrict__ res,
    float* __restrict__ Cf, bf16* __restrict__ Chi, bf16* __restrict__ Clo,
    int M, int N, int K)
{
    extern __shared__ char smem[];
    uint32_t sbase = smem_u32(smem);
    int tid = threadIdx.x, lane = tid & 31, wid = tid >> 5;
    int n0 = blockIdx.x * 128, m0 = blockIdx.y * 128;
    int wm = (wid & 1) * 64, wn = (wid >> 1) * 32;

    const bf16* gAh = Ahi + (size_t)m0 * K;
    const bf16* gAl = Alo + (size_t)m0 * K;
    const bf16* gBh = Bhi + (size_t)n0 * K;
    const bf16* gBl = Blo + (size_t)n0 * K;

    float acc[4][4][4];
    #pragma unroll
    for (int mt = 0; mt < 4; mt++)
        #pragma unroll
        for (int nt = 0; nt < 4; nt++)
            #pragma unroll
            for (int r = 0; r < 4; r++) acc[mt][nt][r] = 0.f;

    int nk = K >> 5;     // BK = 32

    // ---- loader: 8 x 16B cp.async per thread per stage ----
    // j: 0-1 -> Ah, 2-3 -> Al, 4-5 -> Bh, 6-7 -> Bl ; idx = (j&1)*256+tid
    #define STAGE_LOAD(S, KT) do {                                           \
        uint32_t _sb = sbase + (uint32_t)(S) * 40960;                        \
        int _k = (KT) * 32;                                                  \
        _Pragma("unroll")                                                    \
        for (int j = 0; j < 8; j++) {                                        \
            const bf16* _g = (j < 2) ? gAh : (j < 4) ? gAl                   \
                              : (j < 6) ? gBh : gBl;                         \
            int _idx = (j & 1) * 256 + tid;                                  \
            int _row = _idx >> 2, _ch = tid & 3;                             \
            const bf16* _src = _g + (size_t)_row * K + _k + _ch * 8;         \
            uint32_t _dst = _sb + (uint32_t)(j >> 1) * 10240                 \
                          + (uint32_t)_row * 80 + (uint32_t)_ch * 16;        \
            CP_ASYNC16(_dst, _src);                                          \
        }                                                                    \
        CP_COMMIT();                                                         \
    } while (0)

    STAGE_LOAD(0, 0);

    int arow = lane & 15, akoff = (lane >> 4) * 8;
    int bq = lane >> 3;
    int bn = (bq >> 1) * 8 + (lane & 7);
    int bk = (bq & 1) * 8;

    #pragma unroll 1
    for (int kt = 0; kt < nk; kt++) {
        int s = kt & 1;
        if (kt + 1 < nk) { STAGE_LOAD(s ^ 1, kt + 1); CP_WAIT1(); }
        else             { CP_WAIT0(); }
        __syncthreads();

        uint32_t sa = sbase + (uint32_t)s * 40960;
        #pragma unroll
        for (int kh = 0; kh < 2; kh++) {
            int k0 = kh * 16;
            uint32_t ah[4][4], al[4][4], bhf[2][4], blf[2][4];
            #pragma unroll
            for (int mt = 0; mt < 4; mt++) {
                uint32_t addr = sa +
                    (uint32_t)((wm + mt * 16 + arow) * 40 + k0 + akoff) * 2;
                LDMX4(ah[mt], addr);
                LDMX4(al[mt], addr + 10240);
            }
            #pragma unroll
            for (int g = 0; g < 2; g++) {
                uint32_t addr = sa + 20480 +
                    (uint32_t)((wn + g * 16 + bn) * 40 + k0 + bk) * 2;
                LDMX4(bhf[g], addr);
                LDMX4(blf[g], addr + 10240);
            }
            #pragma unroll
            for (int mt = 0; mt < 4; mt++)
                #pragma unroll
                for (int nt = 0; nt < 4; nt++) {
                    int g = nt >> 1, h = (nt & 1) * 2;
                    MMA16816(acc[mt][nt], ah[mt], bhf[g][h], bhf[g][h + 1]);
                    MMA16816(acc[mt][nt], ah[mt], blf[g][h], blf[g][h + 1]);
                    MMA16816(acc[mt][nt], al[mt], bhf[g][h], bhf[g][h + 1]);
                }
        }
        __syncthreads();
    }

    // ---- epilogue ----
    int qrow = lane >> 2, qcol = (lane & 3) * 2;
    #pragma unroll
    for (int mt = 0; mt < 4; mt++) {
        #pragma unroll
        for (int rh = 0; rh < 2; rh++) {
            int row = m0 + wm + mt * 16 + qrow + rh * 8;
            #pragma unroll
            for (int nt = 0; nt < 4; nt++) {
                int col = n0 + wn + nt * 8 + qcol;
                float v0 = acc[mt][nt][rh * 2 + 0] + __ldg(&bias[col]);
                float v1 = acc[mt][nt][rh * 2 + 1] + __ldg(&bias[col + 1]);
                if (ACT == 1) { v0 = gelu_f(v0); v1 = gelu_f(v1); }
                size_t off = (size_t)row * N + col;
                if (RES) {
                    float2 rv = *reinterpret_cast<const float2*>(res + off);
                    v0 += rv.x; v1 += rv.y;
                }
                if (BF16OUT) {
                    bf16 h0, l0, h1, l1;
                    split2(v0, h0, l0); split2(v1, h1, l1);
                    __nv_bfloat162 hh; hh.x = h0; hh.y = h1;
                    __nv_bfloat162 ll; ll.x = l0; ll.y = l1;
                    *reinterpret_cast<__nv_bfloat162*>(Chi + off) = hh;
                    *reinterpret_cast<__nv_bfloat162*>(Clo + off) = ll;
                } else {
                    float2 o; o.x = v0; o.y = v1;
                    *reinterpret_cast<float2*>(Cf + off) = o;
                }
            }
        }
    }
}

// ---------------------------------------------------------------------------
// Flash attention (causal), fp32 in, bf16 hi/lo out
// ---------------------------------------------------------------------------
#define ATTN_SMEM_BYTES 114688

__global__ __launch_bounds__(256) void attn_kernel(
    const float* __restrict__ qkv, bf16* __restrict__ oh, bf16* __restrict__ ol)
{
    extern __shared__ float sm[];
    float* Qt = sm;             // [128][64] d-major
    float* Kt = sm + 8192;      // [128][64] d-major
    float* Vs = sm + 16384;     // [64][128]
    float* Ps = sm + 24576;     // [64][64]

    int qt = blockIdx.x, hh = blockIdx.y, bb = blockIdx.z;
    int tid = threadIdx.x;
    int tx = tid & 15, ty = tid >> 4;
    int lrow = tid >> 2, lchunk = tid & 3;

    const float scale = 0.08838834764831845f;
    const size_t rs = 3 * GPT_H;
    const float* qb = qkv + (size_t)bb * GPT_S * rs + hh * 128;
    const float* kb = qb + GPT_H;
    const float* vb = qb + 2 * GPT_H;
    int q0 = qt * 64;

    {
        const float* src = qb + (size_t)(q0 + lrow) * rs + lchunk * 32;
        #pragma unroll
        for (int j = 0; j < 8; j++) {
            float4 v = *(const float4*)(src + j * 4);
            int d = lchunk * 32 + j * 4;
            Qt[(d + 0) * 64 + lrow] = v.x * scale;
            Qt[(d + 1) * 64 + lrow] = v.y * scale;
            Qt[(d + 2) * 64 + lrow] = v.z * scale;
            Qt[(d + 3) * 64 + lrow] = v.w * scale;
        }
    }

    float m_s[4], l_s[4], O[4][8];
    #pragma unroll
    for (int r = 0; r < 4; r++) {
        m_s[r] = -INFINITY; l_s[r] = 0.f;
        #pragma unroll
        for (int j = 0; j < 8; j++) O[r][j] = 0.f;
    }

    #pragma unroll 1
    for (int kt = 0; kt <= qt; kt++) {
        int k0 = kt * 64;
        __syncthreads();
        {
            const float* ks  = kb + (size_t)(k0 + lrow) * rs + lchunk * 32;
            const float* vsp = vb + (size_t)(k0 + lrow) * rs + lchunk * 32;
            #pragma unroll
            for (int j = 0; j < 8; j++) {
                float4 kv = *(const float4*)(ks + j * 4);
                int d = lchunk * 32 + j * 4;
                Kt[(d + 0) * 64 + lrow] = kv.x;
                Kt[(d + 1) * 64 + lrow] = kv.y;
                Kt[(d + 2) * 64 + lrow] = kv.z;
                Kt[(d + 3) * 64 + lrow] = kv.w;
                float4 vv = *(const float4*)(vsp + j * 4);
                *(float4*)&Vs[lrow * 128 + lchunk * 32 + j * 4] = vv;
            }
        }
        __syncthreads();

        float s[4][4];
        #pragma unroll
        for (int r = 0; r < 4; r++)
            #pragma unroll
            for (int c = 0; c < 4; c++) s[r][c] = 0.f;

        #pragma unroll 4
        for (int d = 0; d < 128; d++) {
            float4 qv = *(const float4*)&Qt[d * 64 + ty * 4];
            float4 kv = *(const float4*)&Kt[d * 64 + tx * 4];
            float qa[4] = {qv.x, qv.y, qv.z, qv.w};
            float ka[4] = {kv.x, kv.y, kv.z, kv.w};
            #pragma unroll
            for (int r = 0; r < 4; r++)
                #pragma unroll
                for (int c = 0; c < 4; c++)
                    s[r][c] += qa[r] * ka[c];
        }

        if (kt == qt) {
            #pragma unroll
            for (int r = 0; r < 4; r++)
                #pragma unroll
                for (int c = 0; c < 4; c++)
                    if (tx * 4 + c > ty * 4 + r) s[r][c] = -INFINITY;
        }

        #pragma unroll
        for (int r = 0; r < 4; r++) {
            float mx = fmaxf(fmaxf(s[r][0], s[r][1]), fmaxf(s[r][2], s[r][3]));
            #pragma unroll
            for (int off = 8; off; off >>= 1)
                mx = fmaxf(mx, __shfl_xor_sync(0xffffffffu, mx, off, 16));
            float mnew = fmaxf(m_s[r], mx);
            float p0 = __expf(s[r][0] - mnew);
            float p1 = __expf(s[r][1] - mnew);
            float p2 = __expf(s[r][2] - mnew);
            float p3 = __expf(s[r][3] - mnew);
            float rsum = p0 + p1 + p2 + p3;
            #pragma unroll
            for (int off = 8; off; off >>= 1)
                rsum += __shfl_xor_sync(0xffffffffu, rsum, off, 16);
            float alpha = __expf(m_s[r] - mnew);
            l_s[r] = l_s[r] * alpha + rsum;
            m_s[r] = mnew;
            #pragma unroll
            for (int j = 0; j < 8; j++) O[r][j] *= alpha;
            *(float4*)&Ps[(ty * 4 + r) * 64 + tx * 4] = make_float4(p0, p1, p2, p3);
        }
        __syncthreads();

        #pragma unroll 4
        for (int k = 0; k < 64; k++) {
            float4 v0 = *(const float4*)&Vs[k * 128 + tx * 4];
            float4 v1 = *(const float4*)&Vs[k * 128 + 64 + tx * 4];
            #pragma unroll
            for (int r = 0; r < 4; r++) {
                float p = Ps[(ty * 4 + r) * 64 + k];
                O[r][0] += p * v0.x; O[r][1] += p * v0.y;
                O[r][2] += p * v0.z; O[r][3] += p * v0.w;
                O[r][4] += p * v1.x; O[r][5] += p * v1.y;
                O[r][6] += p * v1.z; O[r][7] += p * v1.w;
            }
        }
    }

    #pragma unroll
    for (int r = 0; r < 4; r++) {
        float inv = 1.0f / l_s[r];
        size_t base = (size_t)(bb * GPT_S + q0 + ty * 4 + r) * GPT_H + hh * 128;
        #pragma unroll
        for (int g = 0; g < 2; g++) {
            int c0 = g * 64 + tx * 4;
            #pragma unroll
            for (int p = 0; p < 2; p++) {
                float a = O[r][g * 4 + p * 2 + 0] * inv;
                float b = O[r][g * 4 + p * 2 + 1] * inv;
                bf16 h0, l0, h1, l1;
                split2(a, h0, l0); split2(b, h1, l1);
                __nv_bfloat162 hh2; hh2.x = h0; hh2.y = h1;
                __nv_bfloat162 ll2; ll2.x = l0; ll2.y = l1;
                *reinterpret_cast<__nv_bfloat162*>(oh + base + c0 + p * 2) = hh2;
                *reinterpret_cast<__nv_bfloat162*>(ol + base + c0 + p * 2) = ll2;
            }
        }
    }
}

// ---------------------------------------------------------------------------
// launch
// ---------------------------------------------------------------------------
extern "C" void kernel_launch(void* const* d_in, const int* in_sizes, int n_in,
                              void* d_out, int out_size)
{
    const float* x     = (const float*)d_in[0];
    const float* ln1_g = (const float*)d_in[1];
    const float* ln1_b = (const float*)d_in[2];
    const float* ln2_g = (const float*)d_in[3];
    const float* ln2_b = (const float*)d_in[4];
    const float* w_qkv = (const float*)d_in[5];
    const float* b_qkv = (const float*)d_in[6];
    const float* w_ao  = (const float*)d_in[7];
    const float* b_ao  = (const float*)d_in[8];
    const float* w_ff1 = (const float*)d_in[9];
    const float* b_ff1 = (const float*)d_in[10];
    const float* w_ff2 = (const float*)d_in[11];
    const float* b_ff2 = (const float*)d_in[12];
    float* out = (float*)d_out;

    void* p;
    float *qkv, *xmid;
    bf16 *h_hi, *h_lo, *at_hi, *at_lo, *f1_hi, *f1_lo;
    bf16 *wqh, *wql, *waoh, *waol, *wf1h, *wf1l, *wf2h, *wf2l;
    cudaGetSymbolAddress(&p, g_qkv);     qkv   = (float*)p;
    cudaGetSymbolAddress(&p, g_xmid);    xmid  = (float*)p;
    cudaGetSymbolAddress(&p, g_h_hi);    h_hi  = (bf16*)p;
    cudaGetSymbolAddress(&p, g_h_lo);    h_lo  = (bf16*)p;
    cudaGetSymbolAddress(&p, g_at_hi);   at_hi = (bf16*)p;
    cudaGetSymbolAddress(&p, g_at_lo);   at_lo = (bf16*)p;
    cudaGetSymbolAddress(&p, g_f1_hi);   f1_hi = (bf16*)p;
    cudaGetSymbolAddress(&p, g_f1_lo);   f1_lo = (bf16*)p;
    cudaGetSymbolAddress(&p, g_wqkv_hi); wqh   = (bf16*)p;
    cudaGetSymbolAddress(&p, g_wqkv_lo); wql   = (bf16*)p;
    cudaGetSymbolAddress(&p, g_wao_hi);  waoh  = (bf16*)p;
    cudaGetSymbolAddress(&p, g_wao_lo);  waol  = (bf16*)p;
    cudaGetSymbolAddress(&p, g_wf1_hi);  wf1h  = (bf16*)p;
    cudaGetSymbolAddress(&p, g_wf1_lo);  wf1l  = (bf16*)p;
    cudaGetSymbolAddress(&p, g_wf2_hi);  wf2h  = (bf16*)p;
    cudaGetSymbolAddress(&p, g_wf2_lo);  wf2l  = (bf16*)p;

    cudaFuncSetAttribute(attn_kernel,
        cudaFuncAttributeMaxDynamicSharedMemorySize, ATTN_SMEM_BYTES);
    cudaFuncSetAttribute(gemm_mma<0, false, false>,
        cudaFuncAttributeMaxDynamicSharedMemorySize, GEMM_SMEM);
    cudaFuncSetAttribute(gemm_mma<0, true, false>,
        cudaFuncAttributeMaxDynamicSharedMemorySize, GEMM_SMEM);
    cudaFuncSetAttribute(gemm_mma<1, false, true>,
        cudaFuncAttributeMaxDynamicSharedMemorySize, GEMM_SMEM);

    // 0) weight transpose + bf16 split  (W[K,N] -> [N,K] hi/lo)
    wtrans<<<dim3(192, 64),  dim3(32, 8)>>>(w_qkv, wqh, wql, GPT_H, 3 * GPT_H);
    wtrans<<<dim3(64, 64),   dim3(32, 8)>>>(w_ao,  waoh, waol, GPT_H, GPT_H);
    wtrans<<<dim3(256, 64),  dim3(32, 8)>>>(w_ff1, wf1h, wf1l, GPT_H, 4 * GPT_H);
    wtrans<<<dim3(64, 256),  dim3(32, 8)>>>(w_ff2, wf2h, wf2l, 4 * GPT_H, GPT_H);

    // 1) LN1 -> bf16
    ln_kernel<<<GPT_BS, 256>>>(x, ln1_g, ln1_b, h_hi, h_lo);
    // 2) QKV = h @ w_qkv + b  -> fp32   [4096 x 6144 x 2048]
    gemm_mma<0, false, false><<<dim3(48, 32), 256, GEMM_SMEM>>>(
        h_hi, h_lo, wqh, wql, b_qkv, nullptr, qkv, nullptr, nullptr,
        GPT_BS, 3 * GPT_H, GPT_H);
    // 3) attention -> bf16
    attn_kernel<<<dim3(GPT_S / 64, 16, GPT_B), 256, ATTN_SMEM_BYTES>>>(
        qkv, at_hi, at_lo);
    // 4) xmid = x + attn @ w_ao + b  -> fp32   [4096 x 2048 x 2048]
    gemm_mma<0, true, false><<<dim3(16, 32), 256, GEMM_SMEM>>>(
        at_hi, at_lo, waoh, waol, b_ao, x, xmid, nullptr, nullptr,
        GPT_BS, GPT_H, GPT_H);
    // 5) LN2 -> bf16
    ln_kernel<<<GPT_BS, 256>>>(xmid, ln2_g, ln2_b, h_hi, h_lo);
    // 6) ff1 = gelu(h @ w_ff1 + b) -> bf16   [4096 x 8192 x 2048]
    gemm_mma<1, false, true><<<dim3(64, 32), 256, GEMM_SMEM>>>(
        h_hi, h_lo, wf1h, wf1l, b_ff1, nullptr, nullptr, f1_hi, f1_lo,
        GPT_BS, 4 * GPT_H, GPT_H);
    // 7) out = xmid + ff1 @ w_ff2 + b  -> fp32   [4096 x 2048 x 8192]
    gemm_mma<0, true, false><<<dim3(16, 32), 256, GEMM_SMEM>>>(
        f1_hi, f1_lo, wf2h, wf2l, b_ff2, xmid, out, nullptr, nullptr,
        GPT_BS, GPT_H, 4 * GPT_H);
}

// round 11
// speedup vs baseline: 3.9235x; 2.0462x over previous
#include <cuda_runtime.h>
#include <cuda_fp16.h>
#include <stdint.h>
#include <math.h>

// ---------------------------------------------------------------------------
// GPT block (compute_103 base ISA): fp16-split mma.sync GEMMs + HMMA flash attn
// B=2, S=2048, H=2048, NH=16, HD=128
// ---------------------------------------------------------------------------
#define GPT_B  2
#define GPT_S  2048
#define GPT_H  2048
#define GPT_BS 4096

// ---- scratch ----
__device__ float  g_xmid  [(size_t)GPT_BS * GPT_H];
__device__ __half g_qkv_hi[(size_t)GPT_BS * 3 * GPT_H];
__device__ __half g_qkv_lo[(size_t)GPT_BS * 3 * GPT_H];
__device__ __half g_h_hi  [(size_t)GPT_BS * GPT_H];
__device__ __half g_h_lo  [(size_t)GPT_BS * GPT_H];
__device__ __half g_at_hi [(size_t)GPT_BS * GPT_H];
__device__ __half g_at_lo [(size_t)GPT_BS * GPT_H];
__device__ __half g_f1_hi [(size_t)GPT_BS * 4 * GPT_H];
__device__ __half g_f1_lo [(size_t)GPT_BS * 4 * GPT_H];
// transposed fp16 weights [N,K] (hi only)
__device__ __half g_wqkv[(size_t)3 * GPT_H * GPT_H];
__device__ __half g_wao [(size_t)GPT_H * GPT_H];
__device__ __half g_wf1 [(size_t)4 * GPT_H * GPT_H];
__device__ __half g_wf2 [(size_t)4 * GPT_H * GPT_H];

// ---------------------------------------------------------------------------
// PTX helpers (base ISA)
// ---------------------------------------------------------------------------
__device__ __forceinline__ uint32_t smem_u32(const void* p) {
    uint32_t a;
    asm("{ .reg .u64 t; cvta.to.shared.u64 t, %1; cvt.u32.u64 %0, t; }"
        : "=r"(a) : "l"(p));
    return a;
}
#define CP_ASYNC16(dst, src) \
    asm volatile("cp.async.cg.shared.global [%0], [%1], 16;" \
                 :: "r"(dst), "l"(src))
#define CP_COMMIT() asm volatile("cp.async.commit_group;" ::: "memory")
#define CP_WAIT0()  asm volatile("cp.async.wait_group 0;" ::: "memory")
#define CP_WAIT1()  asm volatile("cp.async.wait_group 1;" ::: "memory")

#define LDMX4(r, addr) \
    asm volatile("ldmatrix.sync.aligned.m8n8.x4.shared.b16 {%0,%1,%2,%3}, [%4];" \
        : "=r"((r)[0]), "=r"((r)[1]), "=r"((r)[2]), "=r"((r)[3]) : "r"(addr))
#define LDMX4T(r, addr) \
    asm volatile("ldmatrix.sync.aligned.m8n8.x4.trans.shared.b16 {%0,%1,%2,%3}, [%4];" \
        : "=r"((r)[0]), "=r"((r)[1]), "=r"((r)[2]), "=r"((r)[3]) : "r"(addr))

#define MMAH(d, a, b0, b1) \
    asm volatile("mma.sync.aligned.m16n8k16.row.col.f32.f16.f16.f32 " \
        "{%0,%1,%2,%3}, {%4,%5,%6,%7}, {%8,%9}, {%0,%1,%2,%3};" \
        : "+f"((d)[0]), "+f"((d)[1]), "+f"((d)[2]), "+f"((d)[3]) \
        : "r"((a)[0]), "r"((a)[1]), "r"((a)[2]), "r"((a)[3]), \
          "r"(b0), "r"(b1))

__device__ __forceinline__ void split2h(float x, __half& h, __half& l) {
    h = __float2half_rn(x);
    l = __float2half_rn(x - __half2float(h));
}
__device__ __forceinline__ float gelu_f(float x) {
    float x3 = x * x * x;
    return 0.5f * x * (1.0f + tanhf(0.7978845608028654f * (x + 0.044715f * x3)));
}

// ---------------------------------------------------------------------------
// Weight transpose: W[K,N] fp32 -> T[N,K] fp16
// ---------------------------------------------------------------------------
__global__ __launch_bounds__(256) void wtrans(
    const float* __restrict__ W, __half* __restrict__ Th, int K, int N)
{
    __shared__ float t[32][33];
    int n0 = blockIdx.x * 32, k0 = blockIdx.y * 32;
    int tx = threadIdx.x, ty = threadIdx.y;
    #pragma unroll
    for (int i = 0; i < 32; i += 8)
        t[ty + i][tx] = W[(size_t)(k0 + ty + i) * N + n0 + tx];
    __syncthreads();
    #pragma unroll
    for (int i = 0; i < 32; i += 8)
        Th[(size_t)(n0 + ty + i) * K + k0 + tx] = __float2half_rn(t[tx][ty + i]);
}

// ---------------------------------------------------------------------------
// LayerNorm -> fp16 hi/lo
// ---------------------------------------------------------------------------
__global__ __launch_bounds__(256) void ln_kernel(
    const float* __restrict__ x, const float* __restrict__ gw,
    const float* __restrict__ bw, __half* __restrict__ oh, __half* __restrict__ ol)
{
    int row = blockIdx.x, tid = threadIdx.x;
    const float4* x4 = reinterpret_cast<const float4*>(x + (size_t)row * GPT_H);
    float4 v0 = x4[tid], v1 = x4[tid + 256];
    float sum = v0.x + v0.y + v0.z + v0.w + v1.x + v1.y + v1.z + v1.w;
    float sq  = v0.x*v0.x + v0.y*v0.y + v0.z*v0.z + v0.w*v0.w
              + v1.x*v1.x + v1.y*v1.y + v1.z*v1.z + v1.w*v1.w;
    #pragma unroll
    for (int off = 16; off; off >>= 1) {
        sum += __shfl_xor_sync(0xffffffffu, sum, off);
        sq  += __shfl_xor_sync(0xffffffffu, sq , off);
    }
    __shared__ float ssum[8], ssq[8], s_mu, s_r;
    int wid = tid >> 5;
    if ((tid & 31) == 0) { ssum[wid] = sum; ssq[wid] = sq; }
    __syncthreads();
    if (tid == 0) {
        float ts = 0.f, tq = 0.f;
        #pragma unroll
        for (int i = 0; i < 8; i++) { ts += ssum[i]; tq += ssq[i]; }
        float mu = ts * (1.0f / GPT_H);
        s_mu = mu;
        s_r  = rsqrtf(tq * (1.0f / GPT_H) - mu * mu + 1e-5f);
    }
    __syncthreads();
    float mu = s_mu, r = s_r;
    const float4* g4 = reinterpret_cast<const float4*>(gw);
    const float4* b4 = reinterpret_cast<const float4*>(bw);
    float4 gg0 = g4[tid], gg1 = g4[tid + 256];
    float4 bb0 = b4[tid], bb1 = b4[tid + 256];
    float o[8];
    o[0] = (v0.x - mu) * r * gg0.x + bb0.x;
    o[1] = (v0.y - mu) * r * gg0.y + bb0.y;
    o[2] = (v0.z - mu) * r * gg0.z + bb0.z;
    o[3] = (v0.w - mu) * r * gg0.w + bb0.w;
    o[4] = (v1.x - mu) * r * gg1.x + bb1.x;
    o[5] = (v1.y - mu) * r * gg1.y + bb1.y;
    o[6] = (v1.z - mu) * r * gg1.z + bb1.z;
    o[7] = (v1.w - mu) * r * gg1.w + bb1.w;
    size_t base = (size_t)row * GPT_H;
    #pragma unroll
    for (int g = 0; g < 2; g++) {
        int c0 = (g == 0) ? tid * 4 : (tid + 256) * 4;
        #pragma unroll
        for (int p = 0; p < 2; p++) {
            __half h0, l0, h1, l1;
            split2h(o[g*4 + p*2 + 0], h0, l0);
            split2h(o[g*4 + p*2 + 1], h1, l1);
            __half2 hh; hh.x = h0; hh.y = h1;
            __half2 ll; ll.x = l0; ll.y = l1;
            *reinterpret_cast<__half2*>(oh + base + c0 + p*2) = hh;
            *reinterpret_cast<__half2*>(ol + base + c0 + p*2) = ll;
        }
    }
}

// ---------------------------------------------------------------------------
// fp16x2-split GEMM: C[M,N] = act((Ah+Al) @ Bh^T + bias) (+res)
// 128x128 tile, BK=32, 8 warps, warp tile 64x32.
// Stage: [Ah | Al | Bh] x 10240B, 2 stages = 61440B.
// ---------------------------------------------------------------------------
#define GEMM_SMEM 61440

template<int ACT, bool RES, bool HOUT>
__global__ __launch_bounds__(256) void gemm_mma(
    const __half* __restrict__ Ahi, const __half* __restrict__ Alo,
    const __half* __restrict__ Bhi,
    const float* __restrict__ bias, const float* __restrict__ res,
    float* __restrict__ Cf, __half* __restrict__ Chi, __half* __restrict__ Clo,
    int M, int N, int K)
{
    extern __shared__ char smem[];
    uint32_t sbase = smem_u32(smem);
    int tid = threadIdx.x, lane = tid & 31, wid = tid >> 5;
    int n0 = blockIdx.x * 128, m0 = blockIdx.y * 128;
    int wm = (wid & 1) * 64, wn = (wid >> 1) * 32;

    const __half* gAh = Ahi + (size_t)m0 * K;
    const __half* gAl = Alo + (size_t)m0 * K;
    const __half* gBh = Bhi + (size_t)n0 * K;

    float acc[4][4][4];
    #pragma unroll
    for (int mt = 0; mt < 4; mt++)
        #pragma unroll
        for (int nt = 0; nt < 4; nt++)
            #pragma unroll
            for (int r = 0; r < 4; r++) acc[mt][nt][r] = 0.f;

    int nk = K >> 5;

    #define STAGE_LOAD(S, KT) do {                                           \
        uint32_t _sb = sbase + (uint32_t)(S) * 30720;                        \
        int _k = (KT) * 32;                                                  \
        _Pragma("unroll")                                                    \
        for (int j = 0; j < 6; j++) {                                        \
            const __half* _g = (j < 2) ? gAh : (j < 4) ? gAl : gBh;          \
            int _idx = (j & 1) * 256 + tid;                                  \
            int _row = _idx >> 2, _ch = tid & 3;                             \
            const __half* _src = _g + (size_t)_row * K + _k + _ch * 8;       \
            uint32_t _dst = _sb + (uint32_t)(j >> 1) * 10240                 \
                          + (uint32_t)_row * 80 + (uint32_t)_ch * 16;        \
            CP_ASYNC16(_dst, _src);                                          \
        }                                                                    \
        CP_COMMIT();                                                         \
    } while (0)

    STAGE_LOAD(0, 0);

    int arow = lane & 15, akoff = (lane >> 4) * 8;
    int bq = lane >> 3;
    int bn = (bq >> 1) * 8 + (lane & 7);
    int bk = (bq & 1) * 8;

    #pragma unroll 1
    for (int kt = 0; kt < nk; kt++) {
        int s = kt & 1;
        if (kt + 1 < nk) { STAGE_LOAD(s ^ 1, kt + 1); CP_WAIT1(); }
        else             { CP_WAIT0(); }
        __syncthreads();

        uint32_t sa = sbase + (uint32_t)s * 30720;
        #pragma unroll
        for (int kh = 0; kh < 2; kh++) {
            int k0 = kh * 16;
            uint32_t ah[4][4], al[4][4], bhf[2][4];
            #pragma unroll
            for (int mt = 0; mt < 4; mt++) {
                uint32_t addr = sa +
                    (uint32_t)((wm + mt * 16 + arow) * 40 + k0 + akoff) * 2;
                LDMX4(ah[mt], addr);
                LDMX4(al[mt], addr + 10240);
            }
            #pragma unroll
            for (int g = 0; g < 2; g++) {
                uint32_t addr = sa + 20480 +
                    (uint32_t)((wn + g * 16 + bn) * 40 + k0 + bk) * 2;
                LDMX4(bhf[g], addr);
            }
            #pragma unroll
            for (int mt = 0; mt < 4; mt++)
                #pragma unroll
                for (int nt = 0; nt < 4; nt++) {
                    int g = nt >> 1, h = (nt & 1) * 2;
                    MMAH(acc[mt][nt], ah[mt], bhf[g][h], bhf[g][h + 1]);
                    MMAH(acc[mt][nt], al[mt], bhf[g][h], bhf[g][h + 1]);
                }
        }
        __syncthreads();
    }
    #undef STAGE_LOAD

    int qrow = lane >> 2, qcol = (lane & 3) * 2;
    #pragma unroll
    for (int mt = 0; mt < 4; mt++) {
        #pragma unroll
        for (int rh = 0; rh < 2; rh++) {
            int row = m0 + wm + mt * 16 + qrow + rh * 8;
            #pragma unroll
            for (int nt = 0; nt < 4; nt++) {
                int col = n0 + wn + nt * 8 + qcol;
                float v0 = acc[mt][nt][rh * 2 + 0] + __ldg(&bias[col]);
                float v1 = acc[mt][nt][rh * 2 + 1] + __ldg(&bias[col + 1]);
                if (ACT == 1) { v0 = gelu_f(v0); v1 = gelu_f(v1); }
                size_t off = (size_t)row * N + col;
                if (RES) {
                    float2 rv = *reinterpret_cast<const float2*>(res + off);
                    v0 += rv.x; v1 += rv.y;
                }
                if (HOUT) {
                    __half h0, l0, h1, l1;
                    split2h(v0, h0, l0); split2h(v1, h1, l1);
                    __half2 hh; hh.x = h0; hh.y = h1;
                    __half2 ll; ll.x = l0; ll.y = l1;
                    *reinterpret_cast<__half2*>(Chi + off) = hh;
                    *reinterpret_cast<__half2*>(Clo + off) = ll;
                } else {
                    float2 o; o.x = v0; o.y = v1;
                    *reinterpret_cast<float2*>(Cf + off) = o;
                }
            }
        }
    }
}

// ---------------------------------------------------------------------------
// HMMA flash attention (causal). CTA = (128 q-rows, head, batch), 8 warps.
// Warp w owns S rows 16w..16w+15 (full 64 k-cols)  -> in-warp softmax.
// QK: 3-product fp16 split; PV: P-split x2, V single fp16.
// Smem (halves): Qh[128*136], Ql[128*136], 2 x {Kh,Kl,Vh}[64*136]
// ---------------------------------------------------------------------------
#define ATTN_SMEM 174080
#define QH_OFF 0
#define QL_OFF 17408
#define KV_OFF(s) (34816u + (uint32_t)(s) * 26112u)
#define KL_REL 8704
#define VH_REL 17408

__device__ __forceinline__ void kv_load(
    uint32_t sb, uint32_t kvbase, const __half* qkv_hi, const __half* qkv_lo,
    size_t rowbase, int tid)
{
    const __half* khi = qkv_hi + rowbase + 2048;
    const __half* klo = qkv_lo + rowbase + 2048;
    const __half* vhi = qkv_hi + rowbase + 4096;
    #pragma unroll
    for (int j = 0; j < 4; j++) {
        int idx = j * 256 + tid;
        int r = idx >> 4, ch = idx & 15;
        size_t so = (size_t)r * 6144 + ch * 8;
        uint32_t doff = (uint32_t)(r * 136 + ch * 8);
        CP_ASYNC16(sb + (kvbase + doff) * 2, khi + so);
        CP_ASYNC16(sb + (kvbase + KL_REL + doff) * 2, klo + so);
        CP_ASYNC16(sb + (kvbase + VH_REL + doff) * 2, vhi + so);
    }
}

__global__ __launch_bounds__(256) void attn_mma(
    const __half* __restrict__ qkv_hi, const __half* __restrict__ qkv_lo,
    __half* __restrict__ oh, __half* __restrict__ ol)
{
    extern __shared__ __half smh[];
    uint32_t sb = smem_u32(smh);
    int qt = gridDim.x - 1 - blockIdx.x;          // heavy tiles first
    int hh = blockIdx.y, bb = blockIdx.z;
    int tid = threadIdx.x, lane = tid & 31, wid = tid >> 5;
    int q0 = qt * 128;
    int ktmax = 2 * qt + 2;

    size_t qrowbase = ((size_t)bb * 2048 + q0) * 6144 + hh * 128;

    // Q (hi+lo) -> smem
    #pragma unroll
    for (int j = 0; j < 8; j++) {
        int idx = j * 256 + tid;
        int r = idx >> 4, ch = idx & 15;
        size_t so = qrowbase + (size_t)r * 6144 + ch * 8;
        uint32_t doff = (uint32_t)(r * 136 + ch * 8);
        CP_ASYNC16(sb + (QH_OFF + doff) * 2, qkv_hi + so);
        CP_ASYNC16(sb + (QL_OFF + doff) * 2, qkv_lo + so);
    }
    kv_load(sb, KV_OFF(0), qkv_hi, qkv_lo,
            ((size_t)bb * 2048) * 6144 + hh * 128, tid);
    CP_COMMIT();

    float O[16][4];
    #pragma unroll
    for (int i = 0; i < 16; i++)
        #pragma unroll
        for (int j = 0; j < 4; j++) O[i][j] = 0.f;
    float m0 = -INFINITY, m1 = -INFINITY, l0 = 0.f, l1 = 0.f;

    int arow = lane & 15, akoff = (lane >> 4) * 8;
    int bq = lane >> 3;
    int bn = (bq >> 1) * 8 + (lane & 7);
    int bk = (bq & 1) * 8;
    const float scale = 0.08838834764831845f;

    #pragma unroll 1
    for (int kt = 0; kt < ktmax; kt++) {
        int s = kt & 1;
        if (kt + 1 < ktmax) {
            kv_load(sb, KV_OFF(s ^ 1), qkv_hi, qkv_lo,
                    ((size_t)bb * 2048 + (kt + 1) * 64) * 6144 + hh * 128, tid);
            CP_COMMIT();
            CP_WAIT1();
        } else CP_WAIT0();
        __syncthreads();

        int k0 = kt * 64;
        uint32_t kvb = KV_OFF(s);

        // ---- S = (Qh+Ql)(Kh+Kl)^T : 3 products ----
        float sacc[8][4];
        #pragma unroll
        for (int nt = 0; nt < 8; nt++)
            #pragma unroll
            for (int j = 0; j < 4; j++) sacc[nt][j] = 0.f;

        #pragma unroll
        for (int kc = 0; kc < 8; kc++) {
            uint32_t qaddr = sb +
                (uint32_t)((wid * 16 + arow) * 136 + kc * 16 + akoff) * 2;
            uint32_t ah[4], al[4];
            LDMX4(ah, qaddr);
            LDMX4(al, qaddr + QL_OFF * 2);
            uint32_t kbh[4][4], kbl[4][4];
            #pragma unroll
            for (int g = 0; g < 4; g++) {
                uint32_t addr = sb +
                    (kvb + (uint32_t)((g * 16 + bn) * 136 + kc * 16 + bk)) * 2;
                LDMX4(kbh[g], addr);
                LDMX4(kbl[g], addr + KL_REL * 2);
            }
            #pragma unroll
            for (int nt = 0; nt < 8; nt++) {
                int g = nt >> 1, h = (nt & 1) * 2;
                MMAH(sacc[nt], ah, kbh[g][h], kbh[g][h + 1]);
                MMAH(sacc[nt], ah, kbl[g][h], kbl[g][h + 1]);
                MMAH(sacc[nt], al, kbh[g][h], kbh[g][h + 1]);
            }
        }

        // ---- scale + causal mask ----
        int r0 = q0 + wid * 16 + (lane >> 2);
        if (k0 + 63 > r0 - (lane >> 2) + 0) {   // tile may cross diagonal for this warp
            #pragma unroll
            for (int nt = 0; nt < 8; nt++)
                #pragma unroll
                for (int j = 0; j < 4; j++) {
                    float v = sacc[nt][j] * scale;
                    int col = k0 + nt * 8 + 2 * (lane & 3) + (j & 1);
                    int row = r0 + (j >> 1) * 8;
                    sacc[nt][j] = (col > row) ? -INFINITY : v;
                }
        } else {
            #pragma unroll
            for (int nt = 0; nt < 8; nt++)
                #pragma unroll
                for (int j = 0; j < 4; j++) sacc[nt][j] *= scale;
        }

        // ---- online softmax (rows live in quad groups) ----
        float mx0 = -INFINITY, mx1 = -INFINITY;
        #pragma unroll
        for (int nt = 0; nt < 8; nt++) {
            mx0 = fmaxf(mx0, fmaxf(sacc[nt][0], sacc[nt][1]));
            mx1 = fmaxf(mx1, fmaxf(sacc[nt][2], sacc[nt][3]));
        }
        mx0 = fmaxf(mx0, __shfl_xor_sync(0xffffffffu, mx0, 1));
        mx0 = fmaxf(mx0, __shfl_xor_sync(0xffffffffu, mx0, 2));
        mx1 = fmaxf(mx1, __shfl_xor_sync(0xffffffffu, mx1, 1));
        mx1 = fmaxf(mx1, __shfl_xor_sync(0xffffffffu, mx1, 2));
        float mn0 = fmaxf(m0, mx0), mn1 = fmaxf(m1, mx1);
        float a0 = __expf(m0 - mn0), a1 = __expf(m1 - mn1);
        m0 = mn0; m1 = mn1;
        float rs0 = 0.f, rs1 = 0.f;
        #pragma unroll
        for (int nt = 0; nt < 8; nt++) {
            float p0 = __expf(sacc[nt][0] - mn0);
            float p1 = __expf(sacc[nt][1] - mn0);
            float p2 = __expf(sacc[nt][2] - mn1);
            float p3 = __expf(sacc[nt][3] - mn1);
            sacc[nt][0] = p0; sacc[nt][1] = p1;
            sacc[nt][2] = p2; sacc[nt][3] = p3;
            rs0 += p0 + p1; rs1 += p2 + p3;
        }
        rs0 += __shfl_xor_sync(0xffffffffu, rs0, 1);
        rs0 += __shfl_xor_sync(0xffffffffu, rs0, 2);
        rs1 += __shfl_xor_sync(0xffffffffu, rs1, 1);
        rs1 += __shfl_xor_sync(0xffffffffu, rs1, 2);
        l0 = l0 * a0 + rs0;
        l1 = l1 * a1 + rs1;
        #pragma unroll
        for (int nt2 = 0; nt2 < 16; nt2++) {
            O[nt2][0] *= a0; O[nt2][1] *= a0;
            O[nt2][2] *= a1; O[nt2][3] *= a1;
        }

        // ---- P fragments (in-register, hi/lo) ----
        uint32_t pfh[4][4], pfl[4][4];
        #pragma unroll
        for (int kc2 = 0; kc2 < 4; kc2++) {
            #pragma unroll
            for (int q = 0; q < 4; q++) {
                float v0 = sacc[2 * kc2 + (q >> 1)][(q & 1) * 2 + 0];
                float v1 = sacc[2 * kc2 + (q >> 1)][(q & 1) * 2 + 1];
                // q: 0 -> (r, k0-7), 1 -> (r+8, k0-7), 2 -> (r, k8-15), 3 -> (r+8, k8-15)
                __half h0, h1, lo0, lo1;
                split2h(v0, h0, lo0);
                split2h(v1, h1, lo1);
                __half2 hp; hp.x = h0; hp.y = h1;
                __half2 lp; lp.x = lo0; lp.y = lo1;
                pfh[kc2][q] = *reinterpret_cast<uint32_t*>(&hp);
                pfl[kc2][q] = *reinterpret_cast<uint32_t*>(&lp);
            }
        }
        // fix ordering: a-frag wants {(r,k0-7),(r+8,k0-7),(r,k8-15),(r+8,k8-15)}
        // mapping above: q0=(tile 2kc2, cols j0/j1 row r)=ok; q1=(tile 2kc2 rows r+8);
        // q2=(tile 2kc2+1, row r); q3=(tile 2kc2+1, row r+8)  -> correct.

        // ---- O += P @ V ----
        #pragma unroll
        for (int kc2 = 0; kc2 < 4; kc2++) {
            #pragma unroll
            for (int np = 0; np < 8; np++) {
                uint32_t vb[4];
                uint32_t addr = sb + (kvb + VH_REL +
                    (uint32_t)((kc2 * 16 + (lane & 15)) * 136 +
                               np * 16 + (lane >> 4) * 8)) * 2;
                LDMX4T(vb, addr);
                MMAH(O[2 * np],     pfh[kc2], vb[0], vb[1]);
                MMAH(O[2 * np],     pfl[kc2], vb[0], vb[1]);
                MMAH(O[2 * np + 1], pfh[kc2], vb[2], vb[3]);
                MMAH(O[2 * np + 1], pfl[kc2], vb[2], vb[3]);
            }
        }
        __syncthreads();
    }

    // ---- epilogue: O/l -> fp16 hi/lo ----
    float inv0 = 1.0f / l0, inv1 = 1.0f / l1;
    size_t grow0 = (size_t)bb * 2048 + q0 + wid * 16 + (lane >> 2);
    #pragma unroll
    for (int nt2 = 0; nt2 < 16; nt2++) {
        int c = hh * 128 + nt2 * 8 + 2 * (lane & 3);
        {
            float v0 = O[nt2][0] * inv0, v1 = O[nt2][1] * inv0;
            __half h0, lo0, h1, lo1;
            split2h(v0, h0, lo0); split2h(v1, h1, lo1);
            __half2 hp; hp.x = h0; hp.y = h1;
            __half2 lp; lp.x = lo0; lp.y = lo1;
            *reinterpret_cast<__half2*>(oh + grow0 * 2048 + c) = hp;
            *reinterpret_cast<__half2*>(ol + grow0 * 2048 + c) = lp;
        }
        {
            float v0 = O[nt2][2] * inv1, v1 = O[nt2][3] * inv1;
            __half h0, lo0, h1, lo1;
            split2h(v0, h0, lo0); split2h(v1, h1, lo1);
            __half2 hp; hp.x = h0; hp.y = h1;
            __half2 lp; lp.x = lo0; lp.y = lo1;
            *reinterpret_cast<__half2*>(oh + (grow0 + 8) * 2048 + c) = hp;
            *reinterpret_cast<__half2*>(ol + (grow0 + 8) * 2048 + c) = lp;
        }
    }
}

// ---------------------------------------------------------------------------
// launch
// ---------------------------------------------------------------------------
extern "C" void kernel_launch(void* const* d_in, const int* in_sizes, int n_in,
                              void* d_out, int out_size)
{
    const float* x     = (const float*)d_in[0];
    const float* ln1_g = (const float*)d_in[1];
    const float* ln1_b = (const float*)d_in[2];
    const float* ln2_g = (const float*)d_in[3];
    const float* ln2_b = (const float*)d_in[4];
    const float* w_qkv = (const float*)d_in[5];
    const float* b_qkv = (const float*)d_in[6];
    const float* w_ao  = (const float*)d_in[7];
    const float* b_ao  = (const float*)d_in[8];
    const float* w_ff1 = (const float*)d_in[9];
    const float* b_ff1 = (const float*)d_in[10];
    const float* w_ff2 = (const float*)d_in[11];
    const float* b_ff2 = (const float*)d_in[12];
    float* out = (float*)d_out;

    void* p;
    float* xmid;
    __half *qh, *ql, *h_hi, *h_lo, *at_hi, *at_lo, *f1_hi, *f1_lo;
    __half *wq, *wao, *wf1, *wf2;
    cudaGetSymbolAddress(&p, g_xmid);   xmid  = (float*)p;
    cudaGetSymbolAddress(&p, g_qkv_hi); qh    = (__half*)p;
    cudaGetSymbolAddress(&p, g_qkv_lo); ql    = (__half*)p;
    cudaGetSymbolAddress(&p, g_h_hi);   h_hi  = (__half*)p;
    cudaGetSymbolAddress(&p, g_h_lo);   h_lo  = (__half*)p;
    cudaGetSymbolAddress(&p, g_at_hi);  at_hi = (__half*)p;
    cudaGetSymbolAddress(&p, g_at_lo);  at_lo = (__half*)p;
    cudaGetSymbolAddress(&p, g_f1_hi);  f1_hi = (__half*)p;
    cudaGetSymbolAddress(&p, g_f1_lo);  f1_lo = (__half*)p;
    cudaGetSymbolAddress(&p, g_wqkv);   wq    = (__half*)p;
    cudaGetSymbolAddress(&p, g_wao);    wao   = (__half*)p;
    cudaGetSymbolAddress(&p, g_wf1);    wf1   = (__half*)p;
    cudaGetSymbolAddress(&p, g_wf2);    wf2   = (__half*)p;

    cudaFuncSetAttribute(attn_mma,
        cudaFuncAttributeMaxDynamicSharedMemorySize, ATTN_SMEM);
    cudaFuncSetAttribute(gemm_mma<0, false, true>,
        cudaFuncAttributeMaxDynamicSharedMemorySize, GEMM_SMEM);
    cudaFuncSetAttribute(gemm_mma<0, true, false>,
        cudaFuncAttributeMaxDynamicSharedMemorySize, GEMM_SMEM);
    cudaFuncSetAttribute(gemm_mma<1, false, true>,
        cudaFuncAttributeMaxDynamicSharedMemorySize, GEMM_SMEM);

    // 0) weight transpose (W[K,N] -> [N,K] fp16)
    wtrans<<<dim3(192, 64), dim3(32, 8)>>>(w_qkv, wq,  GPT_H, 3 * GPT_H);
    wtrans<<<dim3(64, 64),  dim3(32, 8)>>>(w_ao,  wao, GPT_H, GPT_H);
    wtrans<<<dim3(256, 64), dim3(32, 8)>>>(w_ff1, wf1, GPT_H, 4 * GPT_H);
    wtrans<<<dim3(64, 256), dim3(32, 8)>>>(w_ff2, wf2, 4 * GPT_H, GPT_H);

    // 1) LN1 -> fp16 hi/lo
    ln_kernel<<<GPT_BS, 256>>>(x, ln1_g, ln1_b, h_hi, h_lo);
    // 2) QKV -> fp16 hi/lo   [4096 x 6144 x 2048]
    gemm_mma<0, false, true><<<dim3(48, 32), 256, GEMM_SMEM>>>(
        h_hi, h_lo, wq, b_qkv, nullptr, nullptr, qh, ql,
        GPT_BS, 3 * GPT_H, GPT_H);
    // 3) HMMA flash attention -> fp16 hi/lo
    attn_mma<<<dim3(GPT_S / 128, 16, GPT_B), 256, ATTN_SMEM>>>(
        qh, ql, at_hi, at_lo);
    // 4) xmid = x + attn @ w_ao + b     [4096 x 2048 x 2048]
    gemm_mma<0, true, false><<<dim3(16, 32), 256, GEMM_SMEM>>>(
        at_hi, at_lo, wao, b_ao, x, xmid, nullptr, nullptr,
        GPT_BS, GPT_H, GPT_H);
    // 5) LN2 -> fp16 hi/lo
    ln_kernel<<<GPT_BS, 256>>>(xmid, ln2_g, ln2_b, h_hi, h_lo);
    // 6) ff1 = gelu(h @ w_ff1 + b) -> fp16 hi/lo  [4096 x 8192 x 2048]
    gemm_mma<1, false, true><<<dim3(64, 32), 256, GEMM_SMEM>>>(
        h_hi, h_lo, wf1, b_ff1, nullptr, nullptr, f1_hi, f1_lo,
        GPT_BS, 4 * GPT_H, GPT_H);
    // 7) out = xmid + ff1 @ w_ff2 + b   [4096 x 2048 x 8192]
    gemm_mma<0, true, false><<<dim3(16, 32), 256, GEMM_SMEM>>>(
        f1_hi, f1_lo, wf2, b_ff2, xmid, out, nullptr, nullptr,
        GPT_BS, GPT_H, 4 * GPT_H);
}

// round 13
// speedup vs baseline: 5.5463x; 1.4136x over previous
#include <cuda_runtime.h>
#include <cuda_fp16.h>
#include <stdint.h>
#include <math.h>

// ---------------------------------------------------------------------------
// GPT block (compute_103 base ISA): fp16-split mma.sync GEMMs + HMMA flash attn
// B=2, S=2048, H=2048, NH=16, HD=128
// ---------------------------------------------------------------------------
#define GPT_B  2
#define GPT_S  2048
#define GPT_H  2048
#define GPT_BS 4096

// ---- scratch ----
__device__ float  g_xmid  [(size_t)GPT_BS * GPT_H];
__device__ __half g_qkv_hi[(size_t)GPT_BS * 3 * GPT_H];
__device__ __half g_qkv_lo[(size_t)GPT_BS * 3 * GPT_H];
__device__ __half g_h_hi  [(size_t)GPT_BS * GPT_H];
__device__ __half g_h_lo  [(size_t)GPT_BS * GPT_H];
__device__ __half g_at_hi [(size_t)GPT_BS * GPT_H];
__device__ __half g_at_lo [(size_t)GPT_BS * GPT_H];
__device__ __half g_f1_hi [(size_t)GPT_BS * 4 * GPT_H];
// transposed fp16 weights [N,K]
__device__ __half g_wqkv[(size_t)3 * GPT_H * GPT_H];
__device__ __half g_wao [(size_t)GPT_H * GPT_H];
__device__ __half g_wf1 [(size_t)4 * GPT_H * GPT_H];
__device__ __half g_wf2 [(size_t)4 * GPT_H * GPT_H];

// ---------------------------------------------------------------------------
// PTX helpers (base ISA)
// ---------------------------------------------------------------------------
__device__ __forceinline__ uint32_t smem_u32(const void* p) {
    uint32_t a;
    asm("{ .reg .u64 t; cvta.to.shared.u64 t, %1; cvt.u32.u64 %0, t; }"
        : "=r"(a) : "l"(p));
    return a;
}
#define CP_ASYNC16(dst, src) \
    asm volatile("cp.async.cg.shared.global [%0], [%1], 16;" \
                 :: "r"(dst), "l"(src))
#define CP_COMMIT() asm volatile("cp.async.commit_group;" ::: "memory")
#define CP_WAIT0()  asm volatile("cp.async.wait_group 0;" ::: "memory")
#define CP_WAIT1()  asm volatile("cp.async.wait_group 1;" ::: "memory")

#define LDMX4(r, addr) \
    asm volatile("ldmatrix.sync.aligned.m8n8.x4.shared.b16 {%0,%1,%2,%3}, [%4];" \
        : "=r"((r)[0]), "=r"((r)[1]), "=r"((r)[2]), "=r"((r)[3]) : "r"(addr))
#define LDMX4T(r, addr) \
    asm volatile("ldmatrix.sync.aligned.m8n8.x4.trans.shared.b16 {%0,%1,%2,%3}, [%4];" \
        : "=r"((r)[0]), "=r"((r)[1]), "=r"((r)[2]), "=r"((r)[3]) : "r"(addr))

#define MMAH(d, a, b0, b1) \
    asm volatile("mma.sync.aligned.m16n8k16.row.col.f32.f16.f16.f32 " \
        "{%0,%1,%2,%3}, {%4,%5,%6,%7}, {%8,%9}, {%0,%1,%2,%3};" \
        : "+f"((d)[0]), "+f"((d)[1]), "+f"((d)[2]), "+f"((d)[3]) \
        : "r"((a)[0]), "r"((a)[1]), "r"((a)[2]), "r"((a)[3]), \
          "r"(b0), "r"(b1))

__device__ __forceinline__ void split2h(float x, __half& h, __half& l) {
    h = __float2half_rn(x);
    l = __float2half_rn(x - __half2float(h));
}
__device__ __forceinline__ float gelu_f(float x) {
    float x3 = x * x * x;
    return 0.5f * x * (1.0f + tanhf(0.7978845608028654f * (x + 0.044715f * x3)));
}

// ---------------------------------------------------------------------------
// Weight transpose: W[K,N] fp32 -> T[N,K] fp16
// ---------------------------------------------------------------------------
__global__ __launch_bounds__(256) void wtrans(
    const float* __restrict__ W, __half* __restrict__ Th, int K, int N)
{
    __shared__ float t[32][33];
    int n0 = blockIdx.x * 32, k0 = blockIdx.y * 32;
    int tx = threadIdx.x, ty = threadIdx.y;
    #pragma unroll
    for (int i = 0; i < 32; i += 8)
        t[ty + i][tx] = W[(size_t)(k0 + ty + i) * N + n0 + tx];
    __syncthreads();
    #pragma unroll
    for (int i = 0; i < 32; i += 8)
        Th[(size_t)(n0 + ty + i) * K + k0 + tx] = __float2half_rn(t[tx][ty + i]);
}

// ---------------------------------------------------------------------------
// LayerNorm -> fp16 hi/lo
// ---------------------------------------------------------------------------
__global__ __launch_bounds__(256) void ln_kernel(
    const float* __restrict__ x, const float* __restrict__ gw,
    const float* __restrict__ bw, __half* __restrict__ oh, __half* __restrict__ ol)
{
    int row = blockIdx.x, tid = threadIdx.x;
    const float4* x4 = reinterpret_cast<const float4*>(x + (size_t)row * GPT_H);
    float4 v0 = x4[tid], v1 = x4[tid + 256];
    float sum = v0.x + v0.y + v0.z + v0.w + v1.x + v1.y + v1.z + v1.w;
    float sq  = v0.x*v0.x + v0.y*v0.y + v0.z*v0.z + v0.w*v0.w
              + v1.x*v1.x + v1.y*v1.y + v1.z*v1.z + v1.w*v1.w;
    #pragma unroll
    for (int off = 16; off; off >>= 1) {
        sum += __shfl_xor_sync(0xffffffffu, sum, off);
        sq  += __shfl_xor_sync(0xffffffffu, sq , off);
    }
    __shared__ float ssum[8], ssq[8], s_mu, s_r;
    int wid = tid >> 5;
    if ((tid & 31) == 0) { ssum[wid] = sum; ssq[wid] = sq; }
    __syncthreads();
    if (tid == 0) {
        float ts = 0.f, tq = 0.f;
        #pragma unroll
        for (int i = 0; i < 8; i++) { ts += ssum[i]; tq += ssq[i]; }
        float mu = ts * (1.0f / GPT_H);
        s_mu = mu;
        s_r  = rsqrtf(tq * (1.0f / GPT_H) - mu * mu + 1e-5f);
    }
    __syncthreads();
    float mu = s_mu, r = s_r;
    const float4* g4 = reinterpret_cast<const float4*>(gw);
    const float4* b4 = reinterpret_cast<const float4*>(bw);
    float4 gg0 = g4[tid], gg1 = g4[tid + 256];
    float4 bb0 = b4[tid], bb1 = b4[tid + 256];
    float o[8];
    o[0] = (v0.x - mu) * r * gg0.x + bb0.x;
    o[1] = (v0.y - mu) * r * gg0.y + bb0.y;
    o[2] = (v0.z - mu) * r * gg0.z + bb0.z;
    o[3] = (v0.w - mu) * r * gg0.w + bb0.w;
    o[4] = (v1.x - mu) * r * gg1.x + bb1.x;
    o[5] = (v1.y - mu) * r * gg1.y + bb1.y;
    o[6] = (v1.z - mu) * r * gg1.z + bb1.z;
    o[7] = (v1.w - mu) * r * gg1.w + bb1.w;
    size_t base = (size_t)row * GPT_H;
    #pragma unroll
    for (int g = 0; g < 2; g++) {
        int c0 = (g == 0) ? tid * 4 : (tid + 256) * 4;
        #pragma unroll
        for (int p = 0; p < 2; p++) {
            __half h0, l0, h1, l1;
            split2h(o[g*4 + p*2 + 0], h0, l0);
            split2h(o[g*4 + p*2 + 1], h1, l1);
            __half2 hh; hh.x = h0; hh.y = h1;
            __half2 ll; ll.x = l0; ll.y = l1;
            *reinterpret_cast<__half2*>(oh + base + c0 + p*2) = hh;
            *reinterpret_cast<__half2*>(ol + base + c0 + p*2) = ll;
        }
    }
}

// ---------------------------------------------------------------------------
// fp16 GEMM: C[M,N] = act(A @ Bh^T + bias) (+res)
// SPLIT: A = Ah + Al (2 MMA products); else A = Ah (1 product).
// 128x128 tile, BK=32, 8 warps, warp tile 64x32, 3-stage cp.async pipeline.
// Stage: [Ah | (Al) | Bh] x 10240B.
// OUTMODE: 0 = fp32, 1 = fp16 hi+lo, 2 = fp16 hi only.
// ---------------------------------------------------------------------------
#define GEMM_SMEM_SPLIT  92160   // 3 * 30720
#define GEMM_SMEM_SINGLE 61440   // 3 * 20480

template<int ACT, bool RES, int OUTMODE, bool SPLIT>
__global__ __launch_bounds__(256) void gemm_mma(
    const __half* __restrict__ Ahi, const __half* __restrict__ Alo,
    const __half* __restrict__ Bhi,
    const float* __restrict__ bias, const float* __restrict__ res,
    float* __restrict__ Cf, __half* __restrict__ Chi, __half* __restrict__ Clo,
    int M, int N, int K)
{
    extern __shared__ char smem[];
    uint32_t sbase = smem_u32(smem);
    const uint32_t STB  = SPLIT ? 30720u : 20480u;    // stage bytes
    const uint32_t BOFF = SPLIT ? 20480u : 10240u;    // B tile offset in stage
    int tid = threadIdx.x, lane = tid & 31, wid = tid >> 5;
    int n0 = blockIdx.x * 128, m0 = blockIdx.y * 128;
    int wm = (wid & 1) * 64, wn = (wid >> 1) * 32;

    const __half* gAh = Ahi + (size_t)m0 * K;
    const __half* gAl = SPLIT ? (Alo + (size_t)m0 * K) : nullptr;
    const __half* gBh = Bhi + (size_t)n0 * K;

    float acc[4][4][4];
    #pragma unroll
    for (int mt = 0; mt < 4; mt++)
        #pragma unroll
        for (int nt = 0; nt < 4; nt++)
            #pragma unroll
            for (int r = 0; r < 4; r++) acc[mt][nt][r] = 0.f;

    int nk = K >> 5;

    #define STAGE_LOAD(S, KT) do {                                           \
        uint32_t _sb = sbase + (uint32_t)(S) * STB;                          \
        int _k = (KT) * 32;                                                  \
        _Pragma("unroll")                                                    \
        for (int j = 0; j < (SPLIT ? 6 : 4); j++) {                          \
            const __half* _g = (j < 2) ? gAh                                 \
                             : (SPLIT && j < 4) ? gAl : gBh;                 \
            int _idx = (j & 1) * 256 + tid;                                  \
            int _row = _idx >> 2, _ch = tid & 3;                             \
            const __half* _src = _g + (size_t)_row * K + _k + _ch * 8;       \
            uint32_t _dst = _sb + (uint32_t)(j >> 1) * 10240                 \
                          + (uint32_t)_row * 80 + (uint32_t)_ch * 16;        \
            CP_ASYNC16(_dst, _src);                                          \
        }                                                                    \
        CP_COMMIT();                                                         \
    } while (0)

    STAGE_LOAD(0, 0);
    STAGE_LOAD(1, 1);          // nk >= 2 always here

    int arow = lane & 15, akoff = (lane >> 4) * 8;
    int bq = lane >> 3;
    int bn = (bq >> 1) * 8 + (lane & 7);
    int bk = (bq & 1) * 8;

    int s = 0;
    #pragma unroll 1
    for (int kt = 0; kt < nk; kt++) {
        if (kt + 1 < nk) CP_WAIT1(); else CP_WAIT0();
        __syncthreads();

        uint32_t sa = sbase + (uint32_t)s * STB;
        #pragma unroll
        for (int kh = 0; kh < 2; kh++) {
            int k0 = kh * 16;
            uint32_t ah[4][4], al[4][4], bhf[2][4];
            #pragma unroll
            for (int mt = 0; mt < 4; mt++) {
                uint32_t addr = sa +
                    (uint32_t)((wm + mt * 16 + arow) * 40 + k0 + akoff) * 2;
                LDMX4(ah[mt], addr);
                if (SPLIT) LDMX4(al[mt], addr + 10240);
            }
            #pragma unroll
            for (int g = 0; g < 2; g++) {
                uint32_t addr = sa + BOFF +
                    (uint32_t)((wn + g * 16 + bn) * 40 + k0 + bk) * 2;
                LDMX4(bhf[g], addr);
            }
            #pragma unroll
            for (int mt = 0; mt < 4; mt++)
                #pragma unroll
                for (int nt = 0; nt < 4; nt++) {
                    int g = nt >> 1, h = (nt & 1) * 2;
                    MMAH(acc[mt][nt], ah[mt], bhf[g][h], bhf[g][h + 1]);
                    if (SPLIT)
                        MMAH(acc[mt][nt], al[mt], bhf[g][h], bhf[g][h + 1]);
                }
        }

        if (kt + 2 < nk) {
            int ns = s + 2; if (ns >= 3) ns -= 3;
            STAGE_LOAD(ns, kt + 2);
        }
        s = (s + 1 == 3) ? 0 : s + 1;
    }
    #undef STAGE_LOAD

    int qrow = lane >> 2, qcol = (lane & 3) * 2;
    #pragma unroll
    for (int mt = 0; mt < 4; mt++) {
        #pragma unroll
        for (int rh = 0; rh < 2; rh++) {
            int row = m0 + wm + mt * 16 + qrow + rh * 8;
            #pragma unroll
            for (int nt = 0; nt < 4; nt++) {
                int col = n0 + wn + nt * 8 + qcol;
                float v0 = acc[mt][nt][rh * 2 + 0] + __ldg(&bias[col]);
                float v1 = acc[mt][nt][rh * 2 + 1] + __ldg(&bias[col + 1]);
                if (ACT == 1) { v0 = gelu_f(v0); v1 = gelu_f(v1); }
                size_t off = (size_t)row * N + col;
                if (RES) {
                    float2 rv = *reinterpret_cast<const float2*>(res + off);
                    v0 += rv.x; v1 += rv.y;
                }
                if (OUTMODE == 1) {
                    __half h0, l0, h1, l1;
                    split2h(v0, h0, l0); split2h(v1, h1, l1);
                    __half2 hh; hh.x = h0; hh.y = h1;
                    __half2 ll; ll.x = l0; ll.y = l1;
                    *reinterpret_cast<__half2*>(Chi + off) = hh;
                    *reinterpret_cast<__half2*>(Clo + off) = ll;
                } else if (OUTMODE == 2) {
                    __half2 hh;
                    hh.x = __float2half_rn(v0);
                    hh.y = __float2half_rn(v1);
                    *reinterpret_cast<__half2*>(Chi + off) = hh;
                } else {
                    float2 o; o.x = v0; o.y = v1;
                    *reinterpret_cast<float2*>(Cf + off) = o;
                }
            }
        }
    }
}

// ---------------------------------------------------------------------------
// HMMA flash attention (causal). CTA = (128 q-rows, head, batch), 8 warps.
// Warp w owns S rows 16w..16w+15 (full 64 k-cols)  -> in-warp softmax.
// QK: 3-product fp16 split; PV: P-split x2, V single fp16.
// ---------------------------------------------------------------------------
#define ATTN_SMEM 174080
#define QH_OFF 0
#define QL_OFF 17408
#define KV_OFF(s) (34816u + (uint32_t)(s) * 26112u)
#define KL_REL 8704
#define VH_REL 17408

__device__ __forceinline__ void kv_load(
    uint32_t sb, uint32_t kvbase, const __half* qkv_hi, const __half* qkv_lo,
    size_t rowbase, int tid)
{
    const __half* khi = qkv_hi + rowbase + 2048;
    const __half* klo = qkv_lo + rowbase + 2048;
    const __half* vhi = qkv_hi + rowbase + 4096;
    #pragma unroll
    for (int j = 0; j < 4; j++) {
        int idx = j * 256 + tid;
        int r = idx >> 4, ch = idx & 15;
        size_t so = (size_t)r * 6144 + ch * 8;
        uint32_t doff = (uint32_t)(r * 136 + ch * 8);
        CP_ASYNC16(sb + (kvbase + doff) * 2, khi + so);
        CP_ASYNC16(sb + (kvbase + KL_REL + doff) * 2, klo + so);
        CP_ASYNC16(sb + (kvbase + VH_REL + doff) * 2, vhi + so);
    }
}

__global__ __launch_bounds__(256) void attn_mma(
    const __half* __restrict__ qkv_hi, const __half* __restrict__ qkv_lo,
    __half* __restrict__ oh, __half* __restrict__ ol)
{
    extern __shared__ __half smh[];
    uint32_t sb = smem_u32(smh);
    int qt = gridDim.x - 1 - blockIdx.x;          // heavy tiles first
    int hh = blockIdx.y, bb = blockIdx.z;
    int tid = threadIdx.x, lane = tid & 31, wid = tid >> 5;
    int q0 = qt * 128;
    int ktmax = 2 * qt + 2;

    size_t qrowbase = ((size_t)bb * 2048 + q0) * 6144 + hh * 128;

    #pragma unroll
    for (int j = 0; j < 8; j++) {
        int idx = j * 256 + tid;
        int r = idx >> 4, ch = idx & 15;
        size_t so = qrowbase + (size_t)r * 6144 + ch * 8;
        uint32_t doff = (uint32_t)(r * 136 + ch * 8);
        CP_ASYNC16(sb + (QH_OFF + doff) * 2, qkv_hi + so);
        CP_ASYNC16(sb + (QL_OFF + doff) * 2, qkv_lo + so);
    }
    kv_load(sb, KV_OFF(0), qkv_hi, qkv_lo,
            ((size_t)bb * 2048) * 6144 + hh * 128, tid);
    CP_COMMIT();

    float O[16][4];
    #pragma unroll
    for (int i = 0; i < 16; i++)
        #pragma unroll
        for (int j = 0; j < 4; j++) O[i][j] = 0.f;
    float m0 = -INFINITY, m1 = -INFINITY, l0 = 0.f, l1 = 0.f;

    int arow = lane & 15, akoff = (lane >> 4) * 8;
    int bq = lane >> 3;
    int bn = (bq >> 1) * 8 + (lane & 7);
    int bk = (bq & 1) * 8;
    const float scale = 0.08838834764831845f;

    #pragma unroll 1
    for (int kt = 0; kt < ktmax; kt++) {
        int s = kt & 1;
        if (kt + 1 < ktmax) {
            kv_load(sb, KV_OFF(s ^ 1), qkv_hi, qkv_lo,
                    ((size_t)bb * 2048 + (kt + 1) * 64) * 6144 + hh * 128, tid);
            CP_COMMIT();
            CP_WAIT1();
        } else CP_WAIT0();
        __syncthreads();

        int k0 = kt * 64;
        uint32_t kvb = KV_OFF(s);

        float sacc[8][4];
        #pragma unroll
        for (int nt = 0; nt < 8; nt++)
            #pragma unroll
            for (int j = 0; j < 4; j++) sacc[nt][j] = 0.f;

        #pragma unroll
        for (int kc = 0; kc < 8; kc++) {
            uint32_t qaddr = sb +
                (uint32_t)((wid * 16 + arow) * 136 + kc * 16 + akoff) * 2;
            uint32_t ah[4], al[4];
            LDMX4(ah, qaddr);
            LDMX4(al, qaddr + QL_OFF * 2);
            uint32_t kbh[4][4], kbl[4][4];
            #pragma unroll
            for (int g = 0; g < 4; g++) {
                uint32_t addr = sb +
                    (kvb + (uint32_t)((g * 16 + bn) * 136 + kc * 16 + bk)) * 2;
                LDMX4(kbh[g], addr);
                LDMX4(kbl[g], addr + KL_REL * 2);
            }
            #pragma unroll
            for (int nt = 0; nt < 8; nt++) {
                int g = nt >> 1, h = (nt & 1) * 2;
                MMAH(sacc[nt], ah, kbh[g][h], kbh[g][h + 1]);
                MMAH(sacc[nt], ah, kbl[g][h], kbl[g][h + 1]);
                MMAH(sacc[nt], al, kbh[g][h], kbh[g][h + 1]);
            }
        }

        int r0 = q0 + wid * 16 + (lane >> 2);
        if (k0 + 63 > r0 - (lane >> 2)) {
            #pragma unroll
            for (int nt = 0; nt < 8; nt++)
                #pragma unroll
                for (int j = 0; j < 4; j++) {
                    float v = sacc[nt][j] * scale;
                    int col = k0 + nt * 8 + 2 * (lane & 3) + (j & 1);
                    int row = r0 + (j >> 1) * 8;
                    sacc[nt][j] = (col > row) ? -INFINITY : v;
                }
        } else {
            #pragma unroll
            for (int nt = 0; nt < 8; nt++)
                #pragma unroll
                for (int j = 0; j < 4; j++) sacc[nt][j] *= scale;
        }

        float mx0 = -INFINITY, mx1 = -INFINITY;
        #pragma unroll
        for (int nt = 0; nt < 8; nt++) {
            mx0 = fmaxf(mx0, fmaxf(sacc[nt][0], sacc[nt][1]));
            mx1 = fmaxf(mx1, fmaxf(sacc[nt][2], sacc[nt][3]));
        }
        mx0 = fmaxf(mx0, __shfl_xor_sync(0xffffffffu, mx0, 1));
        mx0 = fmaxf(mx0, __shfl_xor_sync(0xffffffffu, mx0, 2));
        mx1 = fmaxf(mx1, __shfl_xor_sync(0xffffffffu, mx1, 1));
        mx1 = fmaxf(mx1, __shfl_xor_sync(0xffffffffu, mx1, 2));
        float mn0 = fmaxf(m0, mx0), mn1 = fmaxf(m1, mx1);
        float a0 = __expf(m0 - mn0), a1 = __expf(m1 - mn1);
        m0 = mn0; m1 = mn1;
        float rs0 = 0.f, rs1 = 0.f;
        #pragma unroll
        for (int nt = 0; nt < 8; nt++) {
            float p0 = __expf(sacc[nt][0] - mn0);
            float p1 = __expf(sacc[nt][1] - mn0);
            float p2 = __expf(sacc[nt][2] - mn1);
            float p3 = __expf(sacc[nt][3] - mn1);
            sacc[nt][0] = p0; sacc[nt][1] = p1;
            sacc[nt][2] = p2; sacc[nt][3] = p3;
            rs0 += p0 + p1; rs1 += p2 + p3;
        }
        rs0 += __shfl_xor_sync(0xffffffffu, rs0, 1);
        rs0 += __shfl_xor_sync(0xffffffffu, rs0, 2);
        rs1 += __shfl_xor_sync(0xffffffffu, rs1, 1);
        rs1 += __shfl_xor_sync(0xffffffffu, rs1, 2);
        l0 = l0 * a0 + rs0;
        l1 = l1 * a1 + rs1;
        #pragma unroll
        for (int nt2 = 0; nt2 < 16; nt2++) {
            O[nt2][0] *= a0; O[nt2][1] *= a0;
            O[nt2][2] *= a1; O[nt2][3] *= a1;
        }

        uint32_t pfh[4][4], pfl[4][4];
        #pragma unroll
        for (int kc2 = 0; kc2 < 4; kc2++) {
            #pragma unroll
            for (int q = 0; q < 4; q++) {
                float v0 = sacc[2 * kc2 + (q >> 1)][(q & 1) * 2 + 0];
                float v1 = sacc[2 * kc2 + (q >> 1)][(q & 1) * 2 + 1];
                __half h0, h1, lo0, lo1;
                split2h(v0, h0, lo0);
                split2h(v1, h1, lo1);
                __half2 hp; hp.x = h0; hp.y = h1;
                __half2 lp; lp.x = lo0; lp.y = lo1;
                pfh[kc2][q] = *reinterpret_cast<uint32_t*>(&hp);
                pfl[kc2][q] = *reinterpret_cast<uint32_t*>(&lp);
            }
        }

        #pragma unroll
        for (int kc2 = 0; kc2 < 4; kc2++) {
            #pragma unroll
            for (int np = 0; np < 8; np++) {
                uint32_t vb[4];
                uint32_t addr = sb + (kvb + VH_REL +
                    (uint32_t)((kc2 * 16 + (lane & 15)) * 136 +
                               np * 16 + (lane >> 4) * 8)) * 2;
                LDMX4T(vb, addr);
                MMAH(O[2 * np],     pfh[kc2], vb[0], vb[1]);
                MMAH(O[2 * np],     pfl[kc2], vb[0], vb[1]);
                MMAH(O[2 * np + 1], pfh[kc2], vb[2], vb[3]);
                MMAH(O[2 * np + 1], pfl[kc2], vb[2], vb[3]);
            }
        }
        __syncthreads();
    }

    float inv0 = 1.0f / l0, inv1 = 1.0f / l1;
    size_t grow0 = (size_t)bb * 2048 + q0 + wid * 16 + (lane >> 2);
    #pragma unroll
    for (int nt2 = 0; nt2 < 16; nt2++) {
        int c = hh * 128 + nt2 * 8 + 2 * (lane & 3);
        {
            float v0 = O[nt2][0] * inv0, v1 = O[nt2][1] * inv0;
            __half h0, lo0, h1, lo1;
            split2h(v0, h0, lo0); split2h(v1, h1, lo1);
            __half2 hp; hp.x = h0; hp.y = h1;
            __half2 lp; lp.x = lo0; lp.y = lo1;
            *reinterpret_cast<__half2*>(oh + grow0 * 2048 + c) = hp;
            *reinterpret_cast<__half2*>(ol + grow0 * 2048 + c) = lp;
        }
        {
            float v0 = O[nt2][2] * inv1, v1 = O[nt2][3] * inv1;
            __half h0, lo0, h1, lo1;
            split2h(v0, h0, lo0); split2h(v1, h1, lo1);
            __half2 hp; hp.x = h0; hp.y = h1;
            __half2 lp; lp.x = lo0; lp.y = lo1;
            *reinterpret_cast<__half2*>(oh + (grow0 + 8) * 2048 + c) = hp;
            *reinterpret_cast<__half2*>(ol + (grow0 + 8) * 2048 + c) = lp;
        }
    }
}

// ---------------------------------------------------------------------------
// launch
// ---------------------------------------------------------------------------
extern "C" void kernel_launch(void* const* d_in, const int* in_sizes, int n_in,
                              void* d_out, int out_size)
{
    const float* x     = (const float*)d_in[0];
    const float* ln1_g = (const float*)d_in[1];
    const float* ln1_b = (const float*)d_in[2];
    const float* ln2_g = (const float*)d_in[3];
    const float* ln2_b = (const float*)d_in[4];
    const float* w_qkv = (const float*)d_in[5];
    const float* b_qkv = (const float*)d_in[6];
    const float* w_ao  = (const float*)d_in[7];
    const float* b_ao  = (const float*)d_in[8];
    const float* w_ff1 = (const float*)d_in[9];
    const float* b_ff1 = (const float*)d_in[10];
    const float* w_ff2 = (const float*)d_in[11];
    const float* b_ff2 = (const float*)d_in[12];
    float* out = (float*)d_out;

    void* p;
    float* xmid;
    __half *qh, *ql, *h_hi, *h_lo, *at_hi, *at_lo, *f1_hi;
    __half *wq, *wao, *wf1, *wf2;
    cudaGetSymbolAddress(&p, g_xmid);   xmid  = (float*)p;
    cudaGetSymbolAddress(&p, g_qkv_hi); qh    = (__half*)p;
    cudaGetSymbolAddress(&p, g_qkv_lo); ql    = (__half*)p;
    cudaGetSymbolAddress(&p, g_h_hi);   h_hi  = (__half*)p;
    cudaGetSymbolAddress(&p, g_h_lo);   h_lo  = (__half*)p;
    cudaGetSymbolAddress(&p, g_at_hi);  at_hi = (__half*)p;
    cudaGetSymbolAddress(&p, g_at_lo);  at_lo = (__half*)p;
    cudaGetSymbolAddress(&p, g_f1_hi);  f1_hi = (__half*)p;
    cudaGetSymbolAddress(&p, g_wqkv);   wq    = (__half*)p;
    cudaGetSymbolAddress(&p, g_wao);    wao   = (__half*)p;
    cudaGetSymbolAddress(&p, g_wf1);    wf1   = (__half*)p;
    cudaGetSymbolAddress(&p, g_wf2);    wf2   = (__half*)p;

    cudaFuncSetAttribute(attn_mma,
        cudaFuncAttributeMaxDynamicSharedMemorySize, ATTN_SMEM);
    cudaFuncSetAttribute(gemm_mma<0, false, 1, true>,
        cudaFuncAttributeMaxDynamicSharedMemorySize, GEMM_SMEM_SPLIT);
    cudaFuncSetAttribute(gemm_mma<0, true, 0, true>,
        cudaFuncAttributeMaxDynamicSharedMemorySize, GEMM_SMEM_SPLIT);
    cudaFuncSetAttribute(gemm_mma<1, false, 2, false>,
        cudaFuncAttributeMaxDynamicSharedMemorySize, GEMM_SMEM_SINGLE);
    cudaFuncSetAttribute(gemm_mma<0, true, 0, false>,
        cudaFuncAttributeMaxDynamicSharedMemorySize, GEMM_SMEM_SINGLE);

    // 0) weight transpose (W[K,N] -> [N,K] fp16)
    wtrans<<<dim3(192, 64), dim3(32, 8)>>>(w_qkv, wq,  GPT_H, 3 * GPT_H);
    wtrans<<<dim3(64, 64),  dim3(32, 8)>>>(w_ao,  wao, GPT_H, GPT_H);
    wtrans<<<dim3(256, 64), dim3(32, 8)>>>(w_ff1, wf1, GPT_H, 4 * GPT_H);
    wtrans<<<dim3(64, 256), dim3(32, 8)>>>(w_ff2, wf2, 4 * GPT_H, GPT_H);

    // 1) LN1 -> fp16 hi/lo
    ln_kernel<<<GPT_BS, 256>>>(x, ln1_g, ln1_b, h_hi, h_lo);
    // 2) QKV -> fp16 hi/lo   [4096 x 6144 x 2048]  (2-product)
    gemm_mma<0, false, 1, true><<<dim3(48, 32), 256, GEMM_SMEM_SPLIT>>>(
        h_hi, h_lo, wq, b_qkv, nullptr, nullptr, qh, ql,
        GPT_BS, 3 * GPT_H, GPT_H);
    // 3) HMMA flash attention -> fp16 hi/lo
    attn_mma<<<dim3(GPT_S / 128, 16, GPT_B), 256, ATTN_SMEM>>>(
        qh, ql, at_hi, at_lo);
    // 4) xmid = x + attn @ w_ao + b     [4096 x 2048 x 2048]  (2-product)
    gemm_mma<0, true, 0, true><<<dim3(16, 32), 256, GEMM_SMEM_SPLIT>>>(
        at_hi, at_lo, wao, b_ao, x, xmid, nullptr, nullptr,
        GPT_BS, GPT_H, GPT_H);
    // 5) LN2 -> fp16 hi/lo
    ln_kernel<<<GPT_BS, 256>>>(xmid, ln2_g, ln2_b, h_hi, h_lo);
    // 6) ff1 = gelu(h @ w_ff1 + b) -> fp16 hi   [4096 x 8192 x 2048] (1-product)
    gemm_mma<1, false, 2, false><<<dim3(64, 32), 256, GEMM_SMEM_SINGLE>>>(
        h_hi, nullptr, wf1, b_ff1, nullptr, nullptr, f1_hi, nullptr,
        GPT_BS, 4 * GPT_H, GPT_H);
    // 7) out = xmid + ff1 @ w_ff2 + b   [4096 x 2048 x 8192] (1-product)
    gemm_mma<0, true, 0, false><<<dim3(16, 32), 256, GEMM_SMEM_SINGLE>>>(
        f1_hi, nullptr, wf2, b_ff2, xmid, out, nullptr, nullptr,
        GPT_BS, GPT_H, 4 * GPT_H);
}

// round 14
// speedup vs baseline: 6.3728x; 1.1490x over previous
#include <cuda_runtime.h>
#include <cuda_fp16.h>
#include <stdint.h>
#include <math.h>

// ---------------------------------------------------------------------------
// GPT block (compute_103 base ISA): fp16 mma.sync GEMMs + HMMA flash attn
// B=2, S=2048, H=2048, NH=16, HD=128
// GEMMs: single-product fp16 (incoherent rounding, err ~2e-5/GEMM measured)
// Attention QK: 3-product fp16 split (score precision guards softmax)
// ---------------------------------------------------------------------------
#define GPT_B  2
#define GPT_S  2048
#define GPT_H  2048
#define GPT_BS 4096

// ---- scratch ----
__device__ float  g_xmid  [(size_t)GPT_BS * GPT_H];
__device__ __half g_qkv_hi[(size_t)GPT_BS * 3 * GPT_H];
__device__ __half g_qkv_lo[(size_t)GPT_BS * 3 * GPT_H];
__device__ __half g_h_hi  [(size_t)GPT_BS * GPT_H];
__device__ __half g_at_hi [(size_t)GPT_BS * GPT_H];
__device__ __half g_f1_hi [(size_t)GPT_BS * 4 * GPT_H];
// transposed fp16 weights [N,K]
__device__ __half g_wqkv[(size_t)3 * GPT_H * GPT_H];
__device__ __half g_wao [(size_t)GPT_H * GPT_H];
__device__ __half g_wf1 [(size_t)4 * GPT_H * GPT_H];
__device__ __half g_wf2 [(size_t)4 * GPT_H * GPT_H];

// ---------------------------------------------------------------------------
// PTX helpers (base ISA)
// ---------------------------------------------------------------------------
__device__ __forceinline__ uint32_t smem_u32(const void* p) {
    uint32_t a;
    asm("{ .reg .u64 t; cvta.to.shared.u64 t, %1; cvt.u32.u64 %0, t; }"
        : "=r"(a) : "l"(p));
    return a;
}
#define CP_ASYNC16(dst, src) \
    asm volatile("cp.async.cg.shared.global [%0], [%1], 16;" \
                 :: "r"(dst), "l"(src))
#define CP_COMMIT() asm volatile("cp.async.commit_group;" ::: "memory")
#define CP_WAIT0()  asm volatile("cp.async.wait_group 0;" ::: "memory")
#define CP_WAIT1()  asm volatile("cp.async.wait_group 1;" ::: "memory")

#define LDMX4(r, addr) \
    asm volatile("ldmatrix.sync.aligned.m8n8.x4.shared.b16 {%0,%1,%2,%3}, [%4];" \
        : "=r"((r)[0]), "=r"((r)[1]), "=r"((r)[2]), "=r"((r)[3]) : "r"(addr))
#define LDMX4T(r, addr) \
    asm volatile("ldmatrix.sync.aligned.m8n8.x4.trans.shared.b16 {%0,%1,%2,%3}, [%4];" \
        : "=r"((r)[0]), "=r"((r)[1]), "=r"((r)[2]), "=r"((r)[3]) : "r"(addr))

#define MMAH(d, a, b0, b1) \
    asm volatile("mma.sync.aligned.m16n8k16.row.col.f32.f16.f16.f32 " \
        "{%0,%1,%2,%3}, {%4,%5,%6,%7}, {%8,%9}, {%0,%1,%2,%3};" \
        : "+f"((d)[0]), "+f"((d)[1]), "+f"((d)[2]), "+f"((d)[3]) \
        : "r"((a)[0]), "r"((a)[1]), "r"((a)[2]), "r"((a)[3]), \
          "r"(b0), "r"(b1))

__device__ __forceinline__ void split2h(float x, __half& h, __half& l) {
    h = __float2half_rn(x);
    l = __float2half_rn(x - __half2float(h));
}
__device__ __forceinline__ float gelu_f(float x) {
    float x3 = x * x * x;
    return 0.5f * x * (1.0f + tanhf(0.7978845608028654f * (x + 0.044715f * x3)));
}

// ---------------------------------------------------------------------------
// Weight transpose: W[K,N] fp32 -> T[N,K] fp16
// ---------------------------------------------------------------------------
__global__ __launch_bounds__(256) void wtrans(
    const float* __restrict__ W, __half* __restrict__ Th, int K, int N)
{
    __shared__ float t[32][33];
    int n0 = blockIdx.x * 32, k0 = blockIdx.y * 32;
    int tx = threadIdx.x, ty = threadIdx.y;
    #pragma unroll
    for (int i = 0; i < 32; i += 8)
        t[ty + i][tx] = W[(size_t)(k0 + ty + i) * N + n0 + tx];
    __syncthreads();
    #pragma unroll
    for (int i = 0; i < 32; i += 8)
        Th[(size_t)(n0 + ty + i) * K + k0 + tx] = __float2half_rn(t[tx][ty + i]);
}

// ---------------------------------------------------------------------------
// LayerNorm -> fp16 (hi only)
// ---------------------------------------------------------------------------
__global__ __launch_bounds__(256) void ln_kernel(
    const float* __restrict__ x, const float* __restrict__ gw,
    const float* __restrict__ bw, __half* __restrict__ oh)
{
    int row = blockIdx.x, tid = threadIdx.x;
    const float4* x4 = reinterpret_cast<const float4*>(x + (size_t)row * GPT_H);
    float4 v0 = x4[tid], v1 = x4[tid + 256];
    float sum = v0.x + v0.y + v0.z + v0.w + v1.x + v1.y + v1.z + v1.w;
    float sq  = v0.x*v0.x + v0.y*v0.y + v0.z*v0.z + v0.w*v0.w
              + v1.x*v1.x + v1.y*v1.y + v1.z*v1.z + v1.w*v1.w;
    #pragma unroll
    for (int off = 16; off; off >>= 1) {
        sum += __shfl_xor_sync(0xffffffffu, sum, off);
        sq  += __shfl_xor_sync(0xffffffffu, sq , off);
    }
    __shared__ float ssum[8], ssq[8], s_mu, s_r;
    int wid = tid >> 5;
    if ((tid & 31) == 0) { ssum[wid] = sum; ssq[wid] = sq; }
    __syncthreads();
    if (tid == 0) {
        float ts = 0.f, tq = 0.f;
        #pragma unroll
        for (int i = 0; i < 8; i++) { ts += ssum[i]; tq += ssq[i]; }
        float mu = ts * (1.0f / GPT_H);
        s_mu = mu;
        s_r  = rsqrtf(tq * (1.0f / GPT_H) - mu * mu + 1e-5f);
    }
    __syncthreads();
    float mu = s_mu, r = s_r;
    const float4* g4 = reinterpret_cast<const float4*>(gw);
    const float4* b4 = reinterpret_cast<const float4*>(bw);
    float4 gg0 = g4[tid], gg1 = g4[tid + 256];
    float4 bb0 = b4[tid], bb1 = b4[tid + 256];
    float o[8];
    o[0] = (v0.x - mu) * r * gg0.x + bb0.x;
    o[1] = (v0.y - mu) * r * gg0.y + bb0.y;
    o[2] = (v0.z - mu) * r * gg0.z + bb0.z;
    o[3] = (v0.w - mu) * r * gg0.w + bb0.w;
    o[4] = (v1.x - mu) * r * gg1.x + bb1.x;
    o[5] = (v1.y - mu) * r * gg1.y + bb1.y;
    o[6] = (v1.z - mu) * r * gg1.z + bb1.z;
    o[7] = (v1.w - mu) * r * gg1.w + bb1.w;
    size_t base = (size_t)row * GPT_H;
    #pragma unroll
    for (int g = 0; g < 2; g++) {
        int c0 = (g == 0) ? tid * 4 : (tid + 256) * 4;
        #pragma unroll
        for (int p = 0; p < 2; p++) {
            __half2 hh;
            hh.x = __float2half_rn(o[g*4 + p*2 + 0]);
            hh.y = __float2half_rn(o[g*4 + p*2 + 1]);
            *reinterpret_cast<__half2*>(oh + base + c0 + p*2) = hh;
        }
    }
}

// ---------------------------------------------------------------------------
// fp16 GEMM: C[M,N] = act(A @ B^T + bias) (+res), single product.
// 128x128 tile, BK=32, 8 warps, warp tile 64x32, 3-stage cp.async pipeline.
// Stage: [A | B] x 10240B = 20480B; 3 stages = 61440B.
// OUTMODE: 0 = fp32, 1 = fp16 hi+lo, 2 = fp16 hi only.
// ---------------------------------------------------------------------------
#define GEMM_SMEM 61440

template<int ACT, bool RES, int OUTMODE>
__global__ __launch_bounds__(256) void gemm_mma(
    const __half* __restrict__ Ahi, const __half* __restrict__ Bhi,
    const float* __restrict__ bias, const float* __restrict__ res,
    float* __restrict__ Cf, __half* __restrict__ Chi, __half* __restrict__ Clo,
    int M, int N, int K)
{
    extern __shared__ char smem[];
    uint32_t sbase = smem_u32(smem);
    int tid = threadIdx.x, lane = tid & 31, wid = tid >> 5;
    int n0 = blockIdx.x * 128, m0 = blockIdx.y * 128;
    int wm = (wid & 1) * 64, wn = (wid >> 1) * 32;

    const __half* gAh = Ahi + (size_t)m0 * K;
    const __half* gBh = Bhi + (size_t)n0 * K;

    float acc[4][4][4];
    #pragma unroll
    for (int mt = 0; mt < 4; mt++)
        #pragma unroll
        for (int nt = 0; nt < 4; nt++)
            #pragma unroll
            for (int r = 0; r < 4; r++) acc[mt][nt][r] = 0.f;

    int nk = K >> 5;

    #define STAGE_LOAD(S, KT) do {                                           \
        uint32_t _sb = sbase + (uint32_t)(S) * 20480u;                       \
        int _k = (KT) * 32;                                                  \
        _Pragma("unroll")                                                    \
        for (int j = 0; j < 4; j++) {                                        \
            const __half* _g = (j < 2) ? gAh : gBh;                          \
            int _idx = (j & 1) * 256 + tid;                                  \
            int _row = _idx >> 2, _ch = tid & 3;                             \
            const __half* _src = _g + (size_t)_row * K + _k + _ch * 8;       \
            uint32_t _dst = _sb + (uint32_t)(j >> 1) * 10240                 \
                          + (uint32_t)_row * 80 + (uint32_t)_ch * 16;        \
            CP_ASYNC16(_dst, _src);                                          \
        }                                                                    \
        CP_COMMIT();                                                         \
    } while (0)

    STAGE_LOAD(0, 0);
    STAGE_LOAD(1, 1);

    int arow = lane & 15, akoff = (lane >> 4) * 8;
    int bq = lane >> 3;
    int bn = (bq >> 1) * 8 + (lane & 7);
    int bk = (bq & 1) * 8;

    int s = 0;
    #pragma unroll 1
    for (int kt = 0; kt < nk; kt++) {
        if (kt + 1 < nk) CP_WAIT1(); else CP_WAIT0();
        __syncthreads();

        uint32_t sa = sbase + (uint32_t)s * 20480u;
        #pragma unroll
        for (int kh = 0; kh < 2; kh++) {
            int k0 = kh * 16;
            uint32_t ah[4][4], bhf[2][4];
            #pragma unroll
            for (int mt = 0; mt < 4; mt++) {
                uint32_t addr = sa +
                    (uint32_t)((wm + mt * 16 + arow) * 40 + k0 + akoff) * 2;
                LDMX4(ah[mt], addr);
            }
            #pragma unroll
            for (int g = 0; g < 2; g++) {
                uint32_t addr = sa + 10240u +
                    (uint32_t)((wn + g * 16 + bn) * 40 + k0 + bk) * 2;
                LDMX4(bhf[g], addr);
            }
            #pragma unroll
            for (int mt = 0; mt < 4; mt++)
                #pragma unroll
                for (int nt = 0; nt < 4; nt++) {
                    int g = nt >> 1, h = (nt & 1) * 2;
                    MMAH(acc[mt][nt], ah[mt], bhf[g][h], bhf[g][h + 1]);
                }
        }

        if (kt + 2 < nk) {
            int ns = s + 2; if (ns >= 3) ns -= 3;
            STAGE_LOAD(ns, kt + 2);
        }
        s = (s + 1 == 3) ? 0 : s + 1;
    }
    #undef STAGE_LOAD

    int qrow = lane >> 2, qcol = (lane & 3) * 2;
    #pragma unroll
    for (int mt = 0; mt < 4; mt++) {
        #pragma unroll
        for (int rh = 0; rh < 2; rh++) {
            int row = m0 + wm + mt * 16 + qrow + rh * 8;
            #pragma unroll
            for (int nt = 0; nt < 4; nt++) {
                int col = n0 + wn + nt * 8 + qcol;
                float v0 = acc[mt][nt][rh * 2 + 0] + __ldg(&bias[col]);
                float v1 = acc[mt][nt][rh * 2 + 1] + __ldg(&bias[col + 1]);
                if (ACT == 1) { v0 = gelu_f(v0); v1 = gelu_f(v1); }
                size_t off = (size_t)row * N + col;
                if (RES) {
                    float2 rv = *reinterpret_cast<const float2*>(res + off);
                    v0 += rv.x; v1 += rv.y;
                }
                if (OUTMODE == 1) {
                    __half h0, l0, h1, l1;
                    split2h(v0, h0, l0); split2h(v1, h1, l1);
                    __half2 hh; hh.x = h0; hh.y = h1;
                    __half2 ll; ll.x = l0; ll.y = l1;
                    *reinterpret_cast<__half2*>(Chi + off) = hh;
                    *reinterpret_cast<__half2*>(Clo + off) = ll;
                } else if (OUTMODE == 2) {
                    __half2 hh;
                    hh.x = __float2half_rn(v0);
                    hh.y = __float2half_rn(v1);
                    *reinterpret_cast<__half2*>(Chi + off) = hh;
                } else {
                    float2 o; o.x = v0; o.y = v1;
                    *reinterpret_cast<float2*>(Cf + off) = o;
                }
            }
        }
    }
}

// ---------------------------------------------------------------------------
// HMMA flash attention (causal). CTA = (128 q-rows, head, batch), 8 warps.
// Warp w owns S rows 16w..16w+15 (full 64 k-cols) -> in-warp softmax.
// QK: 3-product fp16 split; PV: P-split x2, V single fp16. Output: hi only.
// ---------------------------------------------------------------------------
#define ATTN_SMEM 174080
#define QH_OFF 0
#define QL_OFF 17408
#define KV_OFF(s) (34816u + (uint32_t)(s) * 26112u)
#define KL_REL 8704
#define VH_REL 17408

__device__ __forceinline__ void kv_load(
    uint32_t sb, uint32_t kvbase, const __half* qkv_hi, const __half* qkv_lo,
    size_t rowbase, int tid)
{
    const __half* khi = qkv_hi + rowbase + 2048;
    const __half* klo = qkv_lo + rowbase + 2048;
    const __half* vhi = qkv_hi + rowbase + 4096;
    #pragma unroll
    for (int j = 0; j < 4; j++) {
        int idx = j * 256 + tid;
        int r = idx >> 4, ch = idx & 15;
        size_t so = (size_t)r * 6144 + ch * 8;
        uint32_t doff = (uint32_t)(r * 136 + ch * 8);
        CP_ASYNC16(sb + (kvbase + doff) * 2, khi + so);
        CP_ASYNC16(sb + (kvbase + KL_REL + doff) * 2, klo + so);
        CP_ASYNC16(sb + (kvbase + VH_REL + doff) * 2, vhi + so);
    }
}

__global__ __launch_bounds__(256) void attn_mma(
    const __half* __restrict__ qkv_hi, const __half* __restrict__ qkv_lo,
    __half* __restrict__ oh)
{
    extern __shared__ __half smh[];
    uint32_t sb = smem_u32(smh);
    int qt = gridDim.x - 1 - blockIdx.x;          // heavy tiles first
    int hh = blockIdx.y, bb = blockIdx.z;
    int tid = threadIdx.x, lane = tid & 31, wid = tid >> 5;
    int q0 = qt * 128;
    int ktmax = 2 * qt + 2;

    size_t qrowbase = ((size_t)bb * 2048 + q0) * 6144 + hh * 128;

    #pragma unroll
    for (int j = 0; j < 8; j++) {
        int idx = j * 256 + tid;
        int r = idx >> 4, ch = idx & 15;
        size_t so = qrowbase + (size_t)r * 6144 + ch * 8;
        uint32_t doff = (uint32_t)(r * 136 + ch * 8);
        CP_ASYNC16(sb + (QH_OFF + doff) * 2, qkv_hi + so);
        CP_ASYNC16(sb + (QL_OFF + doff) * 2, qkv_lo + so);
    }
    kv_load(sb, KV_OFF(0), qkv_hi, qkv_lo,
            ((size_t)bb * 2048) * 6144 + hh * 128, tid);
    CP_COMMIT();

    float O[16][4];
    #pragma unroll
    for (int i = 0; i < 16; i++)
        #pragma unroll
        for (int j = 0; j < 4; j++) O[i][j] = 0.f;
    float m0 = -INFINITY, m1 = -INFINITY, l0 = 0.f, l1 = 0.f;

    int arow = lane & 15, akoff = (lane >> 4) * 8;
    int bq = lane >> 3;
    int bn = (bq >> 1) * 8 + (lane & 7);
    int bk = (bq & 1) * 8;
    const float scale = 0.08838834764831845f;

    #pragma unroll 1
    for (int kt = 0; kt < ktmax; kt++) {
        int s = kt & 1;
        if (kt + 1 < ktmax) {
            kv_load(sb, KV_OFF(s ^ 1), qkv_hi, qkv_lo,
                    ((size_t)bb * 2048 + (kt + 1) * 64) * 6144 + hh * 128, tid);
            CP_COMMIT();
            CP_WAIT1();
        } else CP_WAIT0();
        __syncthreads();

        int k0 = kt * 64;
        uint32_t kvb = KV_OFF(s);

        float sacc[8][4];
        #pragma unroll
        for (int nt = 0; nt < 8; nt++)
            #pragma unroll
            for (int j = 0; j < 4; j++) sacc[nt][j] = 0.f;

        #pragma unroll
        for (int kc = 0; kc < 8; kc++) {
            uint32_t qaddr = sb +
                (uint32_t)((wid * 16 + arow) * 136 + kc * 16 + akoff) * 2;
            uint32_t ah[4], al[4];
            LDMX4(ah, qaddr);
            LDMX4(al, qaddr + QL_OFF * 2);
            uint32_t kbh[4][4], kbl[4][4];
            #pragma unroll
            for (int g = 0; g < 4; g++) {
                uint32_t addr = sb +
                    (kvb + (uint32_t)((g * 16 + bn) * 136 + kc * 16 + bk)) * 2;
                LDMX4(kbh[g], addr);
                LDMX4(kbl[g], addr + KL_REL * 2);
            }
            #pragma unroll
            for (int nt = 0; nt < 8; nt++) {
                int g = nt >> 1, h = (nt & 1) * 2;
                MMAH(sacc[nt], ah, kbh[g][h], kbh[g][h + 1]);
                MMAH(sacc[nt], ah, kbl[g][h], kbl[g][h + 1]);
                MMAH(sacc[nt], al, kbh[g][h], kbh[g][h + 1]);
            }
        }

        int r0 = q0 + wid * 16 + (lane >> 2);
        if (k0 + 63 > r0 - (lane >> 2)) {
            #pragma unroll
            for (int nt = 0; nt < 8; nt++)
                #pragma unroll
                for (int j = 0; j < 4; j++) {
                    float v = sacc[nt][j] * scale;
                    int col = k0 + nt * 8 + 2 * (lane & 3) + (j & 1);
                    int row = r0 + (j >> 1) * 8;
                    sacc[nt][j] = (col > row) ? -INFINITY : v;
                }
        } else {
            #pragma unroll
            for (int nt = 0; nt < 8; nt++)
                #pragma unroll
                for (int j = 0; j < 4; j++) sacc[nt][j] *= scale;
        }

        float mx0 = -INFINITY, mx1 = -INFINITY;
        #pragma unroll
        for (int nt = 0; nt < 8; nt++) {
            mx0 = fmaxf(mx0, fmaxf(sacc[nt][0], sacc[nt][1]));
            mx1 = fmaxf(mx1, fmaxf(sacc[nt][2], sacc[nt][3]));
        }
        mx0 = fmaxf(mx0, __shfl_xor_sync(0xffffffffu, mx0, 1));
        mx0 = fmaxf(mx0, __shfl_xor_sync(0xffffffffu, mx0, 2));
        mx1 = fmaxf(mx1, __shfl_xor_sync(0xffffffffu, mx1, 1));
        mx1 = fmaxf(mx1, __shfl_xor_sync(0xffffffffu, mx1, 2));
        float mn0 = fmaxf(m0, mx0), mn1 = fmaxf(m1, mx1);
        float a0 = __expf(m0 - mn0), a1 = __expf(m1 - mn1);
        m0 = mn0; m1 = mn1;
        float rs0 = 0.f, rs1 = 0.f;
        #pragma unroll
        for (int nt = 0; nt < 8; nt++) {
            float p0 = __expf(sacc[nt][0] - mn0);
            float p1 = __expf(sacc[nt][1] - mn0);
            float p2 = __expf(sacc[nt][2] - mn1);
            float p3 = __expf(sacc[nt][3] - mn1);
            sacc[nt][0] = p0; sacc[nt][1] = p1;
            sacc[nt][2] = p2; sacc[nt][3] = p3;
            rs0 += p0 + p1; rs1 += p2 + p3;
        }
        rs0 += __shfl_xor_sync(0xffffffffu, rs0, 1);
        rs0 += __shfl_xor_sync(0xffffffffu, rs0, 2);
        rs1 += __shfl_xor_sync(0xffffffffu, rs1, 1);
        rs1 += __shfl_xor_sync(0xffffffffu, rs1, 2);
        l0 = l0 * a0 + rs0;
        l1 = l1 * a1 + rs1;
        #pragma unroll
        for (int nt2 = 0; nt2 < 16; nt2++) {
            O[nt2][0] *= a0; O[nt2][1] *= a0;
            O[nt2][2] *= a1; O[nt2][3] *= a1;
        }

        uint32_t pfh[4][4], pfl[4][4];
        #pragma unroll
        for (int kc2 = 0; kc2 < 4; kc2++) {
            #pragma unroll
            for (int q = 0; q < 4; q++) {
                float v0 = sacc[2 * kc2 + (q >> 1)][(q & 1) * 2 + 0];
                float v1 = sacc[2 * kc2 + (q >> 1)][(q & 1) * 2 + 1];
                __half h0, h1, lo0, lo1;
                split2h(v0, h0, lo0);
                split2h(v1, h1, lo1);
                __half2 hp; hp.x = h0; hp.y = h1;
                __half2 lp; lp.x = lo0; lp.y = lo1;
                pfh[kc2][q] = *reinterpret_cast<uint32_t*>(&hp);
                pfl[kc2][q] = *reinterpret_cast<uint32_t*>(&lp);
            }
        }

        #pragma unroll
        for (int kc2 = 0; kc2 < 4; kc2++) {
            #pragma unroll
            for (int np = 0; np < 8; np++) {
                uint32_t vb[4];
                uint32_t addr = sb + (kvb + VH_REL +
                    (uint32_t)((kc2 * 16 + (lane & 15)) * 136 +
                               np * 16 + (lane >> 4) * 8)) * 2;
                LDMX4T(vb, addr);
                MMAH(O[2 * np],     pfh[kc2], vb[0], vb[1]);
                MMAH(O[2 * np],     pfl[kc2], vb[0], vb[1]);
                MMAH(O[2 * np + 1], pfh[kc2], vb[2], vb[3]);
                MMAH(O[2 * np + 1], pfl[kc2], vb[2], vb[3]);
            }
        }
        __syncthreads();
    }

    float inv0 = 1.0f / l0, inv1 = 1.0f / l1;
    size_t grow0 = (size_t)bb * 2048 + q0 + wid * 16 + (lane >> 2);
    #pragma unroll
    for (int nt2 = 0; nt2 < 16; nt2++) {
        int c = hh * 128 + nt2 * 8 + 2 * (lane & 3);
        {
            __half2 hp;
            hp.x = __float2half_rn(O[nt2][0] * inv0);
            hp.y = __float2half_rn(O[nt2][1] * inv0);
            *reinterpret_cast<__half2*>(oh + grow0 * 2048 + c) = hp;
        }
        {
            __half2 hp;
            hp.x = __float2half_rn(O[nt2][2] * inv1);
            hp.y = __float2half_rn(O[nt2][3] * inv1);
            *reinterpret_cast<__half2*>(oh + (grow0 + 8) * 2048 + c) = hp;
        }
    }
}

// ---------------------------------------------------------------------------
// launch
// ---------------------------------------------------------------------------
extern "C" void kernel_launch(void* const* d_in, const int* in_sizes, int n_in,
                              void* d_out, int out_size)
{
    const float* x     = (const float*)d_in[0];
    const float* ln1_g = (const float*)d_in[1];
    const float* ln1_b = (const float*)d_in[2];
    const float* ln2_g = (const float*)d_in[3];
    const float* ln2_b = (const float*)d_in[4];
    const float* w_qkv = (const float*)d_in[5];
    const float* b_qkv = (const float*)d_in[6];
    const float* w_ao  = (const float*)d_in[7];
    const float* b_ao  = (const float*)d_in[8];
    const float* w_ff1 = (const float*)d_in[9];
    const float* b_ff1 = (const float*)d_in[10];
    const float* w_ff2 = (const float*)d_in[11];
    const float* b_ff2 = (const float*)d_in[12];
    float* out = (float*)d_out;

    void* p;
    float* xmid;
    __half *qh, *ql, *h_hi, *at_hi, *f1_hi;
    __half *wq, *wao, *wf1, *wf2;
    cudaGetSymbolAddress(&p, g_xmid);   xmid  = (float*)p;
    cudaGetSymbolAddress(&p, g_qkv_hi); qh    = (__half*)p;
    cudaGetSymbolAddress(&p, g_qkv_lo); ql    = (__half*)p;
    cudaGetSymbolAddress(&p, g_h_hi);   h_hi  = (__half*)p;
    cudaGetSymbolAddress(&p, g_at_hi);  at_hi = (__half*)p;
    cudaGetSymbolAddress(&p, g_f1_hi);  f1_hi = (__half*)p;
    cudaGetSymbolAddress(&p, g_wqkv);   wq    = (__half*)p;
    cudaGetSymbolAddress(&p, g_wao);    wao   = (__half*)p;
    cudaGetSymbolAddress(&p, g_wf1);    wf1   = (__half*)p;
    cudaGetSymbolAddress(&p, g_wf2);    wf2   = (__half*)p;

    cudaFuncSetAttribute(attn_mma,
        cudaFuncAttributeMaxDynamicSharedMemorySize, ATTN_SMEM);
    cudaFuncSetAttribute(gemm_mma<0, false, 1>,
        cudaFuncAttributeMaxDynamicSharedMemorySize, GEMM_SMEM);
    cudaFuncSetAttribute(gemm_mma<0, true, 0>,
        cudaFuncAttributeMaxDynamicSharedMemorySize, GEMM_SMEM);
    cudaFuncSetAttribute(gemm_mma<1, false, 2>,
        cudaFuncAttributeMaxDynamicSharedMemorySize, GEMM_SMEM);

    // 0) weight transpose (W[K,N] -> [N,K] fp16)
    wtrans<<<dim3(192, 64), dim3(32, 8)>>>(w_qkv, wq,  GPT_H, 3 * GPT_H);
    wtrans<<<dim3(64, 64),  dim3(32, 8)>>>(w_ao,  wao, GPT_H, GPT_H);
    wtrans<<<dim3(256, 64), dim3(32, 8)>>>(w_ff1, wf1, GPT_H, 4 * GPT_H);
    wtrans<<<dim3(64, 256), dim3(32, 8)>>>(w_ff2, wf2, 4 * GPT_H, GPT_H);

    // 1) LN1 -> fp16 hi
    ln_kernel<<<GPT_BS, 256>>>(x, ln1_g, ln1_b, h_hi);
    // 2) QKV -> fp16 hi/lo   [4096 x 6144 x 2048]
    gemm_mma<0, false, 1><<<dim3(48, 32), 256, GEMM_SMEM>>>(
        h_hi, wq, b_qkv, nullptr, nullptr, qh, ql,
        GPT_BS, 3 * GPT_H, GPT_H);
    // 3) HMMA flash attention -> fp16 hi
    attn_mma<<<dim3(GPT_S / 128, 16, GPT_B), 256, ATTN_SMEM>>>(
        qh, ql, at_hi);
    // 4) xmid = x + attn @ w_ao + b     [4096 x 2048 x 2048]
    gemm_mma<0, true, 0><<<dim3(16, 32), 256, GEMM_SMEM>>>(
        at_hi, wao, b_ao, x, xmid, nullptr, nullptr,
        GPT_BS, GPT_H, GPT_H);
    // 5) LN2 -> fp16 hi
    ln_kernel<<<GPT_BS, 256>>>(xmid, ln2_g, ln2_b, h_hi);
    // 6) ff1 = gelu(h @ w_ff1 + b) -> fp16 hi   [4096 x 8192 x 2048]
    gemm_mma<1, false, 2><<<dim3(64, 32), 256, GEMM_SMEM>>>(
        h_hi, wf1, b_ff1, nullptr, nullptr, f1_hi, nullptr,
        GPT_BS, 4 * GPT_H, GPT_H);
    // 7) out = xmid + ff1 @ w_ff2 + b   [4096 x 2048 x 8192]
    gemm_mma<0, true, 0><<<dim3(16, 32), 256, GEMM_SMEM>>>(
        f1_hi, wf2, b_ff2, xmid, out, nullptr, nullptr,
        GPT_BS, GPT_H, 4 * GPT_H);
}

// round 15
// speedup vs baseline: 7.0366x; 1.1042x over previous
#include <cuda_runtime.h>
#include <cuda_fp16.h>
#include <stdint.h>
#include <math.h>

// ---------------------------------------------------------------------------
// GPT block (compute_103 base ISA): fp16 mma.sync GEMMs + single-fp16 HMMA
// flash attention. B=2, S=2048, H=2048, NH=16, HD=128
// Error model (measured R12/R13): incoherent fp16 rounding self-averages at
// K=2048+; single-product everywhere keeps e2e rel_err ~1e-4 vs 1e-3 budget.
// ---------------------------------------------------------------------------
#define GPT_B  2
#define GPT_S  2048
#define GPT_H  2048
#define GPT_BS 4096

// ---- scratch ----
__device__ float  g_xmid  [(size_t)GPT_BS * GPT_H];
__device__ __half g_qkv_hi[(size_t)GPT_BS * 3 * GPT_H];
__device__ __half g_h_hi  [(size_t)GPT_BS * GPT_H];
__device__ __half g_at_hi [(size_t)GPT_BS * GPT_H];
__device__ __half g_f1_hi [(size_t)GPT_BS * 4 * GPT_H];
// transposed fp16 weights [N,K]
__device__ __half g_wqkv[(size_t)3 * GPT_H * GPT_H];
__device__ __half g_wao [(size_t)GPT_H * GPT_H];
__device__ __half g_wf1 [(size_t)4 * GPT_H * GPT_H];
__device__ __half g_wf2 [(size_t)4 * GPT_H * GPT_H];

// ---------------------------------------------------------------------------
// PTX helpers (base ISA)
// ---------------------------------------------------------------------------
__device__ __forceinline__ uint32_t smem_u32(const void* p) {
    uint32_t a;
    asm("{ .reg .u64 t; cvta.to.shared.u64 t, %1; cvt.u32.u64 %0, t; }"
        : "=r"(a) : "l"(p));
    return a;
}
#define CP_ASYNC16(dst, src) \
    asm volatile("cp.async.cg.shared.global [%0], [%1], 16;" \
                 :: "r"(dst), "l"(src))
#define CP_COMMIT() asm volatile("cp.async.commit_group;" ::: "memory")
#define CP_WAIT0()  asm volatile("cp.async.wait_group 0;" ::: "memory")
#define CP_WAIT1()  asm volatile("cp.async.wait_group 1;" ::: "memory")

#define LDMX4(r, addr) \
    asm volatile("ldmatrix.sync.aligned.m8n8.x4.shared.b16 {%0,%1,%2,%3}, [%4];" \
        : "=r"((r)[0]), "=r"((r)[1]), "=r"((r)[2]), "=r"((r)[3]) : "r"(addr))
#define LDMX4T(r, addr) \
    asm volatile("ldmatrix.sync.aligned.m8n8.x4.trans.shared.b16 {%0,%1,%2,%3}, [%4];" \
        : "=r"((r)[0]), "=r"((r)[1]), "=r"((r)[2]), "=r"((r)[3]) : "r"(addr))

#define MMAH(d, a, b0, b1) \
    asm volatile("mma.sync.aligned.m16n8k16.row.col.f32.f16.f16.f32 " \
        "{%0,%1,%2,%3}, {%4,%5,%6,%7}, {%8,%9}, {%0,%1,%2,%3};" \
        : "+f"((d)[0]), "+f"((d)[1]), "+f"((d)[2]), "+f"((d)[3]) \
        : "r"((a)[0]), "r"((a)[1]), "r"((a)[2]), "r"((a)[3]), \
          "r"(b0), "r"(b1))

__device__ __forceinline__ float gelu_f(float x) {
    float x3 = x * x * x;
    return 0.5f * x * (1.0f + tanhf(0.7978845608028654f * (x + 0.044715f * x3)));
}

// ---------------------------------------------------------------------------
// Weight transpose: W[K,N] fp32 -> T[N,K] fp16
// ---------------------------------------------------------------------------
__global__ __launch_bounds__(256) void wtrans(
    const float* __restrict__ W, __half* __restrict__ Th, int K, int N)
{
    __shared__ float t[32][33];
    int n0 = blockIdx.x * 32, k0 = blockIdx.y * 32;
    int tx = threadIdx.x, ty = threadIdx.y;
    #pragma unroll
    for (int i = 0; i < 32; i += 8)
        t[ty + i][tx] = W[(size_t)(k0 + ty + i) * N + n0 + tx];
    __syncthreads();
    #pragma unroll
    for (int i = 0; i < 32; i += 8)
        Th[(size_t)(n0 + ty + i) * K + k0 + tx] = __float2half_rn(t[tx][ty + i]);
}

// ---------------------------------------------------------------------------
// LayerNorm -> fp16
// ---------------------------------------------------------------------------
__global__ __launch_bounds__(256) void ln_kernel(
    const float* __restrict__ x, const float* __restrict__ gw,
    const float* __restrict__ bw, __half* __restrict__ oh)
{
    int row = blockIdx.x, tid = threadIdx.x;
    const float4* x4 = reinterpret_cast<const float4*>(x + (size_t)row * GPT_H);
    float4 v0 = x4[tid], v1 = x4[tid + 256];
    float sum = v0.x + v0.y + v0.z + v0.w + v1.x + v1.y + v1.z + v1.w;
    float sq  = v0.x*v0.x + v0.y*v0.y + v0.z*v0.z + v0.w*v0.w
              + v1.x*v1.x + v1.y*v1.y + v1.z*v1.z + v1.w*v1.w;
    #pragma unroll
    for (int off = 16; off; off >>= 1) {
        sum += __shfl_xor_sync(0xffffffffu, sum, off);
        sq  += __shfl_xor_sync(0xffffffffu, sq , off);
    }
    __shared__ float ssum[8], ssq[8], s_mu, s_r;
    int wid = tid >> 5;
    if ((tid & 31) == 0) { ssum[wid] = sum; ssq[wid] = sq; }
    __syncthreads();
    if (tid == 0) {
        float ts = 0.f, tq = 0.f;
        #pragma unroll
        for (int i = 0; i < 8; i++) { ts += ssum[i]; tq += ssq[i]; }
        float mu = ts * (1.0f / GPT_H);
        s_mu = mu;
        s_r  = rsqrtf(tq * (1.0f / GPT_H) - mu * mu + 1e-5f);
    }
    __syncthreads();
    float mu = s_mu, r = s_r;
    const float4* g4 = reinterpret_cast<const float4*>(gw);
    const float4* b4 = reinterpret_cast<const float4*>(bw);
    float4 gg0 = g4[tid], gg1 = g4[tid + 256];
    float4 bb0 = b4[tid], bb1 = b4[tid + 256];
    float o[8];
    o[0] = (v0.x - mu) * r * gg0.x + bb0.x;
    o[1] = (v0.y - mu) * r * gg0.y + bb0.y;
    o[2] = (v0.z - mu) * r * gg0.z + bb0.z;
    o[3] = (v0.w - mu) * r * gg0.w + bb0.w;
    o[4] = (v1.x - mu) * r * gg1.x + bb1.x;
    o[5] = (v1.y - mu) * r * gg1.y + bb1.y;
    o[6] = (v1.z - mu) * r * gg1.z + bb1.z;
    o[7] = (v1.w - mu) * r * gg1.w + bb1.w;
    size_t base = (size_t)row * GPT_H;
    #pragma unroll
    for (int g = 0; g < 2; g++) {
        int c0 = (g == 0) ? tid * 4 : (tid + 256) * 4;
        #pragma unroll
        for (int p = 0; p < 2; p++) {
            __half2 hh;
            hh.x = __float2half_rn(o[g*4 + p*2 + 0]);
            hh.y = __float2half_rn(o[g*4 + p*2 + 1]);
            *reinterpret_cast<__half2*>(oh + base + c0 + p*2) = hh;
        }
    }
}

// ---------------------------------------------------------------------------
// fp16 GEMM: C[M,N] = act(A @ B^T + bias) (+res), single product.
// 128x128 tile, BK=32, 8 warps, warp tile 64x32, 3-stage cp.async pipeline.
// OUTMODE: 0 = fp32, 2 = fp16.
// ---------------------------------------------------------------------------
#define GEMM_SMEM 61440

template<int ACT, bool RES, int OUTMODE>
__global__ __launch_bounds__(256) void gemm_mma(
    const __half* __restrict__ Ahi, const __half* __restrict__ Bhi,
    const float* __restrict__ bias, const float* __restrict__ res,
    float* __restrict__ Cf, __half* __restrict__ Chi,
    int M, int N, int K)
{
    extern __shared__ char smem[];
    uint32_t sbase = smem_u32(smem);
    int tid = threadIdx.x, lane = tid & 31, wid = tid >> 5;
    int n0 = blockIdx.x * 128, m0 = blockIdx.y * 128;
    int wm = (wid & 1) * 64, wn = (wid >> 1) * 32;

    const __half* gAh = Ahi + (size_t)m0 * K;
    const __half* gBh = Bhi + (size_t)n0 * K;

    float acc[4][4][4];
    #pragma unroll
    for (int mt = 0; mt < 4; mt++)
        #pragma unroll
        for (int nt = 0; nt < 4; nt++)
            #pragma unroll
            for (int r = 0; r < 4; r++) acc[mt][nt][r] = 0.f;

    int nk = K >> 5;

    #define STAGE_LOAD(S, KT) do {                                           \
        uint32_t _sb = sbase + (uint32_t)(S) * 20480u;                       \
        int _k = (KT) * 32;                                                  \
        _Pragma("unroll")                                                    \
        for (int j = 0; j < 4; j++) {                                        \
            const __half* _g = (j < 2) ? gAh : gBh;                          \
            int _idx = (j & 1) * 256 + tid;                                  \
            int _row = _idx >> 2, _ch = tid & 3;                             \
            const __half* _src = _g + (size_t)_row * K + _k + _ch * 8;       \
            uint32_t _dst = _sb + (uint32_t)(j >> 1) * 10240                 \
                          + (uint32_t)_row * 80 + (uint32_t)_ch * 16;        \
            CP_ASYNC16(_dst, _src);                                          \
        }                                                                    \
        CP_COMMIT();                                                         \
    } while (0)

    STAGE_LOAD(0, 0);
    STAGE_LOAD(1, 1);

    int arow = lane & 15, akoff = (lane >> 4) * 8;
    int bq = lane >> 3;
    int bn = (bq >> 1) * 8 + (lane & 7);
    int bk = (bq & 1) * 8;

    int s = 0;
    #pragma unroll 1
    for (int kt = 0; kt < nk; kt++) {
        if (kt + 1 < nk) CP_WAIT1(); else CP_WAIT0();
        __syncthreads();

        uint32_t sa = sbase + (uint32_t)s * 20480u;
        #pragma unroll
        for (int kh = 0; kh < 2; kh++) {
            int k0 = kh * 16;
            uint32_t ah[4][4], bhf[2][4];
            #pragma unroll
            for (int mt = 0; mt < 4; mt++) {
                uint32_t addr = sa +
                    (uint32_t)((wm + mt * 16 + arow) * 40 + k0 + akoff) * 2;
                LDMX4(ah[mt], addr);
            }
            #pragma unroll
            for (int g = 0; g < 2; g++) {
                uint32_t addr = sa + 10240u +
                    (uint32_t)((wn + g * 16 + bn) * 40 + k0 + bk) * 2;
                LDMX4(bhf[g], addr);
            }
            #pragma unroll
            for (int mt = 0; mt < 4; mt++)
                #pragma unroll
                for (int nt = 0; nt < 4; nt++) {
                    int g = nt >> 1, h = (nt & 1) * 2;
                    MMAH(acc[mt][nt], ah[mt], bhf[g][h], bhf[g][h + 1]);
                }
        }

        if (kt + 2 < nk) {
            int ns = s + 2; if (ns >= 3) ns -= 3;
            STAGE_LOAD(ns, kt + 2);
        }
        s = (s + 1 == 3) ? 0 : s + 1;
    }
    #undef STAGE_LOAD

    int qrow = lane >> 2, qcol = (lane & 3) * 2;
    #pragma unroll
    for (int mt = 0; mt < 4; mt++) {
        #pragma unroll
        for (int rh = 0; rh < 2; rh++) {
            int row = m0 + wm + mt * 16 + qrow + rh * 8;
            #pragma unroll
            for (int nt = 0; nt < 4; nt++) {
                int col = n0 + wn + nt * 8 + qcol;
                float v0 = acc[mt][nt][rh * 2 + 0] + __ldg(&bias[col]);
                float v1 = acc[mt][nt][rh * 2 + 1] + __ldg(&bias[col + 1]);
                if (ACT == 1) { v0 = gelu_f(v0); v1 = gelu_f(v1); }
                size_t off = (size_t)row * N + col;
                if (RES) {
                    float2 rv = *reinterpret_cast<const float2*>(res + off);
                    v0 += rv.x; v1 += rv.y;
                }
                if (OUTMODE == 2) {
                    __half2 hh;
                    hh.x = __float2half_rn(v0);
                    hh.y = __float2half_rn(v1);
                    *reinterpret_cast<__half2*>(Chi + off) = hh;
                } else {
                    float2 o; o.x = v0; o.y = v1;
                    *reinterpret_cast<float2*>(Cf + off) = o;
                }
            }
        }
    }
}

// ---------------------------------------------------------------------------
// HMMA flash attention (causal), single fp16. CTA = (128 q-rows, head, batch),
// 8 warps; warp w owns S rows 16w..16w+15 (full 64 k-cols) -> in-warp softmax.
// Smem (halves): Qh[128*136]=17408, 2 x {Kh,Vh}[64*136 each]=17408/stage.
// ---------------------------------------------------------------------------
#define ATTN_SMEM 104448
#define QH_OFF 0
#define KV_OFF(s) (17408u + (uint32_t)(s) * 17408u)
#define VH_REL 8704

__device__ __forceinline__ void kv_load(
    uint32_t sb, uint32_t kvbase, const __half* qkv_hi,
    size_t rowbase, int tid)
{
    const __half* khi = qkv_hi + rowbase + 2048;
    const __half* vhi = qkv_hi + rowbase + 4096;
    #pragma unroll
    for (int j = 0; j < 4; j++) {
        int idx = j * 256 + tid;
        int r = idx >> 4, ch = idx & 15;
        size_t so = (size_t)r * 6144 + ch * 8;
        uint32_t doff = (uint32_t)(r * 136 + ch * 8);
        CP_ASYNC16(sb + (kvbase + doff) * 2, khi + so);
        CP_ASYNC16(sb + (kvbase + VH_REL + doff) * 2, vhi + so);
    }
}

__global__ __launch_bounds__(256) void attn_mma(
    const __half* __restrict__ qkv_hi, __half* __restrict__ oh)
{
    extern __shared__ __half smh[];
    uint32_t sb = smem_u32(smh);
    int qt = gridDim.x - 1 - blockIdx.x;          // heavy tiles first
    int hh = blockIdx.y, bb = blockIdx.z;
    int tid = threadIdx.x, lane = tid & 31, wid = tid >> 5;
    int q0 = qt * 128;
    int ktmax = 2 * qt + 2;

    size_t qrowbase = ((size_t)bb * 2048 + q0) * 6144 + hh * 128;

    #pragma unroll
    for (int j = 0; j < 8; j++) {
        int idx = j * 256 + tid;
        int r = idx >> 4, ch = idx & 15;
        size_t so = qrowbase + (size_t)r * 6144 + ch * 8;
        uint32_t doff = (uint32_t)(r * 136 + ch * 8);
        CP_ASYNC16(sb + (QH_OFF + doff) * 2, qkv_hi + so);
    }
    kv_load(sb, KV_OFF(0), qkv_hi,
            ((size_t)bb * 2048) * 6144 + hh * 128, tid);
    CP_COMMIT();

    float O[16][4];
    #pragma unroll
    for (int i = 0; i < 16; i++)
        #pragma unroll
        for (int j = 0; j < 4; j++) O[i][j] = 0.f;
    float m0 = -INFINITY, m1 = -INFINITY, l0 = 0.f, l1 = 0.f;

    int arow = lane & 15, akoff = (lane >> 4) * 8;
    int bq = lane >> 3;
    int bn = (bq >> 1) * 8 + (lane & 7);
    int bk = (bq & 1) * 8;
    const float scale = 0.08838834764831845f;

    #pragma unroll 1
    for (int kt = 0; kt < ktmax; kt++) {
        int s = kt & 1;
        if (kt + 1 < ktmax) {
            kv_load(sb, KV_OFF(s ^ 1), qkv_hi,
                    ((size_t)bb * 2048 + (kt + 1) * 64) * 6144 + hh * 128, tid);
            CP_COMMIT();
            CP_WAIT1();
        } else CP_WAIT0();
        __syncthreads();

        int k0 = kt * 64;
        uint32_t kvb = KV_OFF(s);

        float sacc[8][4];
        #pragma unroll
        for (int nt = 0; nt < 8; nt++)
            #pragma unroll
            for (int j = 0; j < 4; j++) sacc[nt][j] = 0.f;

        #pragma unroll
        for (int kc = 0; kc < 8; kc++) {
            uint32_t qaddr = sb +
                (uint32_t)((wid * 16 + arow) * 136 + kc * 16 + akoff) * 2;
            uint32_t ah[4];
            LDMX4(ah, qaddr);
            uint32_t kbh[4][4];
            #pragma unroll
            for (int g = 0; g < 4; g++) {
                uint32_t addr = sb +
                    (kvb + (uint32_t)((g * 16 + bn) * 136 + kc * 16 + bk)) * 2;
                LDMX4(kbh[g], addr);
            }
            #pragma unroll
            for (int nt = 0; nt < 8; nt++) {
                int g = nt >> 1, h = (nt & 1) * 2;
                MMAH(sacc[nt], ah, kbh[g][h], kbh[g][h + 1]);
            }
        }

        int r0 = q0 + wid * 16 + (lane >> 2);
        if (k0 + 63 > r0 - (lane >> 2)) {
            #pragma unroll
            for (int nt = 0; nt < 8; nt++)
                #pragma unroll
                for (int j = 0; j < 4; j++) {
                    float v = sacc[nt][j] * scale;
                    int col = k0 + nt * 8 + 2 * (lane & 3) + (j & 1);
                    int row = r0 + (j >> 1) * 8;
                    sacc[nt][j] = (col > row) ? -INFINITY : v;
                }
        } else {
            #pragma unroll
            for (int nt = 0; nt < 8; nt++)
                #pragma unroll
                for (int j = 0; j < 4; j++) sacc[nt][j] *= scale;
        }

        float mx0 = -INFINITY, mx1 = -INFINITY;
        #pragma unroll
        for (int nt = 0; nt < 8; nt++) {
            mx0 = fmaxf(mx0, fmaxf(sacc[nt][0], sacc[nt][1]));
            mx1 = fmaxf(mx1, fmaxf(sacc[nt][2], sacc[nt][3]));
        }
        mx0 = fmaxf(mx0, __shfl_xor_sync(0xffffffffu, mx0, 1));
        mx0 = fmaxf(mx0, __shfl_xor_sync(0xffffffffu, mx0, 2));
        mx1 = fmaxf(mx1, __shfl_xor_sync(0xffffffffu, mx1, 1));
        mx1 = fmaxf(mx1, __shfl_xor_sync(0xffffffffu, mx1, 2));
        float mn0 = fmaxf(m0, mx0), mn1 = fmaxf(m1, mx1);
        float a0 = __expf(m0 - mn0), a1 = __expf(m1 - mn1);
        m0 = mn0; m1 = mn1;
        float rs0 = 0.f, rs1 = 0.f;
        #pragma unroll
        for (int nt = 0; nt < 8; nt++) {
            float p0 = __expf(sacc[nt][0] - mn0);
            float p1 = __expf(sacc[nt][1] - mn0);
            float p2 = __expf(sacc[nt][2] - mn1);
            float p3 = __expf(sacc[nt][3] - mn1);
            sacc[nt][0] = p0; sacc[nt][1] = p1;
            sacc[nt][2] = p2; sacc[nt][3] = p3;
            rs0 += p0 + p1; rs1 += p2 + p3;
        }
        rs0 += __shfl_xor_sync(0xffffffffu, rs0, 1);
        rs0 += __shfl_xor_sync(0xffffffffu, rs0, 2);
        rs1 += __shfl_xor_sync(0xffffffffu, rs1, 1);
        rs1 += __shfl_xor_sync(0xffffffffu, rs1, 2);
        l0 = l0 * a0 + rs0;
        l1 = l1 * a1 + rs1;
        #pragma unroll
        for (int nt2 = 0; nt2 < 16; nt2++) {
            O[nt2][0] *= a0; O[nt2][1] *= a0;
            O[nt2][2] *= a1; O[nt2][3] *= a1;
        }

        uint32_t pfh[4][4];
        #pragma unroll
        for (int kc2 = 0; kc2 < 4; kc2++) {
            #pragma unroll
            for (int q = 0; q < 4; q++) {
                float v0 = sacc[2 * kc2 + (q >> 1)][(q & 1) * 2 + 0];
                float v1 = sacc[2 * kc2 + (q >> 1)][(q & 1) * 2 + 1];
                __half2 hp;
                hp.x = __float2half_rn(v0);
                hp.y = __float2half_rn(v1);
                pfh[kc2][q] = *reinterpret_cast<uint32_t*>(&hp);
            }
        }

        #pragma unroll
        for (int kc2 = 0; kc2 < 4; kc2++) {
            #pragma unroll
            for (int np = 0; np < 8; np++) {
                uint32_t vb[4];
                uint32_t addr = sb + (kvb + VH_REL +
                    (uint32_t)((kc2 * 16 + (lane & 15)) * 136 +
                               np * 16 + (lane >> 4) * 8)) * 2;
                LDMX4T(vb, addr);
                MMAH(O[2 * np],     pfh[kc2], vb[0], vb[1]);
                MMAH(O[2 * np + 1], pfh[kc2], vb[2], vb[3]);
            }
        }
        __syncthreads();
    }

    float inv0 = 1.0f / l0, inv1 = 1.0f / l1;
    size_t grow0 = (size_t)bb * 2048 + q0 + wid * 16 + (lane >> 2);
    #pragma unroll
    for (int nt2 = 0; nt2 < 16; nt2++) {
        int c = hh * 128 + nt2 * 8 + 2 * (lane & 3);
        {
            __half2 hp;
            hp.x = __float2half_rn(O[nt2][0] * inv0);
            hp.y = __float2half_rn(O[nt2][1] * inv0);
            *reinterpret_cast<__half2*>(oh + grow0 * 2048 + c) = hp;
        }
        {
            __half2 hp;
            hp.x = __float2half_rn(O[nt2][2] * inv1);
            hp.y = __float2half_rn(O[nt2][3] * inv1);
            *reinterpret_cast<__half2*>(oh + (grow0 + 8) * 2048 + c) = hp;
        }
    }
}

// ---------------------------------------------------------------------------
// launch
// ---------------------------------------------------------------------------
extern "C" void kernel_launch(void* const* d_in, const int* in_sizes, int n_in,
                              void* d_out, int out_size)
{
    const float* x     = (const float*)d_in[0];
    const float* ln1_g = (const float*)d_in[1];
    const float* ln1_b = (const float*)d_in[2];
    const float* ln2_g = (const float*)d_in[3];
    const float* ln2_b = (const float*)d_in[4];
    const float* w_qkv = (const float*)d_in[5];
    const float* b_qkv = (const float*)d_in[6];
    const float* w_ao  = (const float*)d_in[7];
    const float* b_ao  = (const float*)d_in[8];
    const float* w_ff1 = (const float*)d_in[9];
    const float* b_ff1 = (const float*)d_in[10];
    const float* w_ff2 = (const float*)d_in[11];
    const float* b_ff2 = (const float*)d_in[12];
    float* out = (float*)d_out;

    void* p;
    float* xmid;
    __half *qh, *h_hi, *at_hi, *f1_hi;
    __half *wq, *wao, *wf1, *wf2;
    cudaGetSymbolAddress(&p, g_xmid);   xmid  = (float*)p;
    cudaGetSymbolAddress(&p, g_qkv_hi); qh    = (__half*)p;
    cudaGetSymbolAddress(&p, g_h_hi);   h_hi  = (__half*)p;
    cudaGetSymbolAddress(&p, g_at_hi);  at_hi = (__half*)p;
    cudaGetSymbolAddress(&p, g_f1_hi);  f1_hi = (__half*)p;
    cudaGetSymbolAddress(&p, g_wqkv);   wq    = (__half*)p;
    cudaGetSymbolAddress(&p, g_wao);    wao   = (__half*)p;
    cudaGetSymbolAddress(&p, g_wf1);    wf1   = (__half*)p;
    cudaGetSymbolAddress(&p, g_wf2);    wf2   = (__half*)p;

    cudaFuncSetAttribute(attn_mma,
        cudaFuncAttributeMaxDynamicSharedMemorySize, ATTN_SMEM);
    cudaFuncSetAttribute(gemm_mma<0, false, 2>,
        cudaFuncAttributeMaxDynamicSharedMemorySize, GEMM_SMEM);
    cudaFuncSetAttribute(gemm_mma<0, true, 0>,
        cudaFuncAttributeMaxDynamicSharedMemorySize, GEMM_SMEM);
    cudaFuncSetAttribute(gemm_mma<1, false, 2>,
        cudaFuncAttributeMaxDynamicSharedMemorySize, GEMM_SMEM);

    // 0) weight transpose (W[K,N] -> [N,K] fp16)
    wtrans<<<dim3(192, 64), dim3(32, 8)>>>(w_qkv, wq,  GPT_H, 3 * GPT_H);
    wtrans<<<dim3(64, 64),  dim3(32, 8)>>>(w_ao,  wao, GPT_H, GPT_H);
    wtrans<<<dim3(256, 64), dim3(32, 8)>>>(w_ff1, wf1, GPT_H, 4 * GPT_H);
    wtrans<<<dim3(64, 256), dim3(32, 8)>>>(w_ff2, wf2, 4 * GPT_H, GPT_H);

    // 1) LN1 -> fp16
    ln_kernel<<<GPT_BS, 256>>>(x, ln1_g, ln1_b, h_hi);
    // 2) QKV -> fp16   [4096 x 6144 x 2048]
    gemm_mma<0, false, 2><<<dim3(48, 32), 256, GEMM_SMEM>>>(
        h_hi, wq, b_qkv, nullptr, nullptr, qh,
        GPT_BS, 3 * GPT_H, GPT_H);
    // 3) HMMA flash attention -> fp16
    attn_mma<<<dim3(GPT_S / 128, 16, GPT_B), 256, ATTN_SMEM>>>(qh, at_hi);
    // 4) xmid = x + attn @ w_ao + b     [4096 x 2048 x 2048]
    gemm_mma<0, true, 0><<<dim3(16, 32), 256, GEMM_SMEM>>>(
        at_hi, wao, b_ao, x, xmid, nullptr,
        GPT_BS, GPT_H, GPT_H);
    // 5) LN2 -> fp16
    ln_kernel<<<GPT_BS, 256>>>(xmid, ln2_g, ln2_b, h_hi);
    // 6) ff1 = gelu(h @ w_ff1 + b) -> fp16   [4096 x 8192 x 2048]
    gemm_mma<1, false, 2><<<dim3(64, 32), 256, GEMM_SMEM>>>(
        h_hi, wf1, b_ff1, nullptr, nullptr, f1_hi,
        GPT_BS, 4 * GPT_H, GPT_H);
    // 7) out = xmid + ff1 @ w_ff2 + b   [4096 x 2048 x 8192]
    gemm_mma<0, true, 0><<<dim3(16, 32), 256, GEMM_SMEM>>>(
        f1_hi, wf2, b_ff2, xmid, out, nullptr,
        GPT_BS, GPT_H, 4 * GPT_H);
}

// round 16
// speedup vs baseline: 7.5743x; 1.0764x over previous
#include <cuda_runtime.h>
#include <cuda_fp16.h>
#include <stdint.h>
#include <math.h>

// ---------------------------------------------------------------------------
// GPT block (compute_103 base ISA): fp16 mma.sync GEMMs + single-fp16 HMMA
// flash attention. B=2, S=2048, H=2048, NH=16, HD=128
// Error model (measured R12-R14): incoherent fp16 rounding self-averages at
// K=2048+; single-product everywhere keeps e2e rel_err ~8.5e-5 vs 1e-3 budget.
// ---------------------------------------------------------------------------
#define GPT_B  2
#define GPT_S  2048
#define GPT_H  2048
#define GPT_BS 4096

// ---- scratch ----
__device__ float  g_xmid  [(size_t)GPT_BS * GPT_H];
__device__ __half g_qkv_hi[(size_t)GPT_BS * 3 * GPT_H];
__device__ __half g_h_hi  [(size_t)GPT_BS * GPT_H];
__device__ __half g_at_hi [(size_t)GPT_BS * GPT_H];
__device__ __half g_f1_hi [(size_t)GPT_BS * 4 * GPT_H];
// transposed fp16 weights [N,K]
__device__ __half g_wqkv[(size_t)3 * GPT_H * GPT_H];
__device__ __half g_wao [(size_t)GPT_H * GPT_H];
__device__ __half g_wf1 [(size_t)4 * GPT_H * GPT_H];
__device__ __half g_wf2 [(size_t)4 * GPT_H * GPT_H];

// ---------------------------------------------------------------------------
// PTX helpers (base ISA)
// ---------------------------------------------------------------------------
__device__ __forceinline__ uint32_t smem_u32(const void* p) {
    uint32_t a;
    asm("{ .reg .u64 t; cvta.to.shared.u64 t, %1; cvt.u32.u64 %0, t; }"
        : "=r"(a) : "l"(p));
    return a;
}
#define CP_ASYNC16(dst, src) \
    asm volatile("cp.async.cg.shared.global [%0], [%1], 16;" \
                 :: "r"(dst), "l"(src))
#define CP_COMMIT() asm volatile("cp.async.commit_group;" ::: "memory")
#define CP_WAIT0()  asm volatile("cp.async.wait_group 0;" ::: "memory")
#define CP_WAIT1()  asm volatile("cp.async.wait_group 1;" ::: "memory")

#define LDMX4(r, addr) \
    asm volatile("ldmatrix.sync.aligned.m8n8.x4.shared.b16 {%0,%1,%2,%3}, [%4];" \
        : "=r"((r)[0]), "=r"((r)[1]), "=r"((r)[2]), "=r"((r)[3]) : "r"(addr))
#define LDMX4T(r, addr) \
    asm volatile("ldmatrix.sync.aligned.m8n8.x4.trans.shared.b16 {%0,%1,%2,%3}, [%4];" \
        : "=r"((r)[0]), "=r"((r)[1]), "=r"((r)[2]), "=r"((r)[3]) : "r"(addr))

#define MMAH(d, a, b0, b1) \
    asm volatile("mma.sync.aligned.m16n8k16.row.col.f32.f16.f16.f32 " \
        "{%0,%1,%2,%3}, {%4,%5,%6,%7}, {%8,%9}, {%0,%1,%2,%3};" \
        : "+f"((d)[0]), "+f"((d)[1]), "+f"((d)[2]), "+f"((d)[3]) \
        : "r"((a)[0]), "r"((a)[1]), "r"((a)[2]), "r"((a)[3]), \
          "r"(b0), "r"(b1))

__device__ __forceinline__ float gelu_f(float x) {
    float x3 = x * x * x;
    return 0.5f * x * (1.0f + tanhf(0.7978845608028654f * (x + 0.044715f * x3)));
}

// ---------------------------------------------------------------------------
// Fused weight transpose: all four W[K,N] fp32 -> T[N,K] fp16 in ONE launch.
// Linear block id dispatches into 4 segments (32x32 tiles each).
// ---------------------------------------------------------------------------
#define WT_QKV_TILES 12288   // 192 x 64
#define WT_AO_TILES   4096   //  64 x 64
#define WT_FF1_TILES 16384   // 256 x 64
#define WT_FF2_TILES 16384   //  64 x 256
#define WT_TOTAL (WT_QKV_TILES + WT_AO_TILES + WT_FF1_TILES + WT_FF2_TILES)

__global__ __launch_bounds__(256) void wtrans_all(
    const float* __restrict__ Wq, __half* __restrict__ Tq,
    const float* __restrict__ Wa, __half* __restrict__ Ta,
    const float* __restrict__ Wf1, __half* __restrict__ Tf1,
    const float* __restrict__ Wf2, __half* __restrict__ Tf2)
{
    int id = blockIdx.x;
    const float* W; __half* T; int K, N, bx, by;
    if (id < WT_QKV_TILES) {
        W = Wq; T = Tq; K = GPT_H; N = 3 * GPT_H;
        bx = id % 192; by = id / 192;
    } else if (id < WT_QKV_TILES + WT_AO_TILES) {
        id -= WT_QKV_TILES;
        W = Wa; T = Ta; K = GPT_H; N = GPT_H;
        bx = id % 64; by = id / 64;
    } else if (id < WT_QKV_TILES + WT_AO_TILES + WT_FF1_TILES) {
        id -= WT_QKV_TILES + WT_AO_TILES;
        W = Wf1; T = Tf1; K = GPT_H; N = 4 * GPT_H;
        bx = id % 256; by = id / 256;
    } else {
        id -= WT_QKV_TILES + WT_AO_TILES + WT_FF1_TILES;
        W = Wf2; T = Tf2; K = 4 * GPT_H; N = GPT_H;
        bx = id % 64; by = id / 64;
    }

    __shared__ float t[32][33];
    int n0 = bx * 32, k0 = by * 32;
    int tx = threadIdx.x & 31, ty = threadIdx.x >> 5;
    #pragma unroll
    for (int i = 0; i < 32; i += 8)
        t[ty + i][tx] = W[(size_t)(k0 + ty + i) * N + n0 + tx];
    __syncthreads();
    #pragma unroll
    for (int i = 0; i < 32; i += 8)
        T[(size_t)(n0 + ty + i) * K + k0 + tx] = __float2half_rn(t[tx][ty + i]);
}

// ---------------------------------------------------------------------------
// LayerNorm -> fp16
// ---------------------------------------------------------------------------
__global__ __launch_bounds__(256) void ln_kernel(
    const float* __restrict__ x, const float* __restrict__ gw,
    const float* __restrict__ bw, __half* __restrict__ oh)
{
    int row = blockIdx.x, tid = threadIdx.x;
    const float4* x4 = reinterpret_cast<const float4*>(x + (size_t)row * GPT_H);
    float4 v0 = x4[tid], v1 = x4[tid + 256];
    float sum = v0.x + v0.y + v0.z + v0.w + v1.x + v1.y + v1.z + v1.w;
    float sq  = v0.x*v0.x + v0.y*v0.y + v0.z*v0.z + v0.w*v0.w
              + v1.x*v1.x + v1.y*v1.y + v1.z*v1.z + v1.w*v1.w;
    #pragma unroll
    for (int off = 16; off; off >>= 1) {
        sum += __shfl_xor_sync(0xffffffffu, sum, off);
        sq  += __shfl_xor_sync(0xffffffffu, sq , off);
    }
    __shared__ float ssum[8], ssq[8], s_mu, s_r;
    int wid = tid >> 5;
    if ((tid & 31) == 0) { ssum[wid] = sum; ssq[wid] = sq; }
    __syncthreads();
    if (tid == 0) {
        float ts = 0.f, tq = 0.f;
        #pragma unroll
        for (int i = 0; i < 8; i++) { ts += ssum[i]; tq += ssq[i]; }
        float mu = ts * (1.0f / GPT_H);
        s_mu = mu;
        s_r  = rsqrtf(tq * (1.0f / GPT_H) - mu * mu + 1e-5f);
    }
    __syncthreads();
    float mu = s_mu, r = s_r;
    const float4* g4 = reinterpret_cast<const float4*>(gw);
    const float4* b4 = reinterpret_cast<const float4*>(bw);
    float4 gg0 = g4[tid], gg1 = g4[tid + 256];
    float4 bb0 = b4[tid], bb1 = b4[tid + 256];
    float o[8];
    o[0] = (v0.x - mu) * r * gg0.x + bb0.x;
    o[1] = (v0.y - mu) * r * gg0.y + bb0.y;
    o[2] = (v0.z - mu) * r * gg0.z + bb0.z;
    o[3] = (v0.w - mu) * r * gg0.w + bb0.w;
    o[4] = (v1.x - mu) * r * gg1.x + bb1.x;
    o[5] = (v1.y - mu) * r * gg1.y + bb1.y;
    o[6] = (v1.z - mu) * r * gg1.z + bb1.z;
    o[7] = (v1.w - mu) * r * gg1.w + bb1.w;
    size_t base = (size_t)row * GPT_H;
    #pragma unroll
    for (int g = 0; g < 2; g++) {
        int c0 = (g == 0) ? tid * 4 : (tid + 256) * 4;
        #pragma unroll
        for (int p = 0; p < 2; p++) {
            __half2 hh;
            hh.x = __float2half_rn(o[g*4 + p*2 + 0]);
            hh.y = __float2half_rn(o[g*4 + p*2 + 1]);
            *reinterpret_cast<__half2*>(oh + base + c0 + p*2) = hh;
        }
    }
}

// ---------------------------------------------------------------------------
// fp16 GEMM: C[M,N] = act(A @ B^T + bias) (+res), single product.
// 128x128 tile, BK=32, 8 warps, warp tile 64x32, 3-stage cp.async pipeline.
// __launch_bounds__(256,2): cap regs at 128 -> 2 CTAs/SM to hide sync bubbles.
// OUTMODE: 0 = fp32, 2 = fp16.
// ---------------------------------------------------------------------------
#define GEMM_SMEM 61440

template<int ACT, bool RES, int OUTMODE>
__global__ __launch_bounds__(256, 2) void gemm_mma(
    const __half* __restrict__ Ahi, const __half* __restrict__ Bhi,
    const float* __restrict__ bias, const float* __restrict__ res,
    float* __restrict__ Cf, __half* __restrict__ Chi,
    int M, int N, int K)
{
    extern __shared__ char smem[];
    uint32_t sbase = smem_u32(smem);
    int tid = threadIdx.x, lane = tid & 31, wid = tid >> 5;
    int n0 = blockIdx.x * 128, m0 = blockIdx.y * 128;
    int wm = (wid & 1) * 64, wn = (wid >> 1) * 32;

    const __half* gAh = Ahi + (size_t)m0 * K;
    const __half* gBh = Bhi + (size_t)n0 * K;

    float acc[4][4][4];
    #pragma unroll
    for (int mt = 0; mt < 4; mt++)
        #pragma unroll
        for (int nt = 0; nt < 4; nt++)
            #pragma unroll
            for (int r = 0; r < 4; r++) acc[mt][nt][r] = 0.f;

    int nk = K >> 5;

    #define STAGE_LOAD(S, KT) do {                                           \
        uint32_t _sb = sbase + (uint32_t)(S) * 20480u;                       \
        int _k = (KT) * 32;                                                  \
        _Pragma("unroll")                                                    \
        for (int j = 0; j < 4; j++) {                                        \
            const __half* _g = (j < 2) ? gAh : gBh;                          \
            int _idx = (j & 1) * 256 + tid;                                  \
            int _row = _idx >> 2, _ch = tid & 3;                             \
            const __half* _src = _g + (size_t)_row * K + _k + _ch * 8;       \
            uint32_t _dst = _sb + (uint32_t)(j >> 1) * 10240                 \
                          + (uint32_t)_row * 80 + (uint32_t)_ch * 16;        \
            CP_ASYNC16(_dst, _src);                                          \
        }                                                                    \
        CP_COMMIT();                                                         \
    } while (0)

    STAGE_LOAD(0, 0);
    STAGE_LOAD(1, 1);

    int arow = lane & 15, akoff = (lane >> 4) * 8;
    int bq = lane >> 3;
    int bn = (bq >> 1) * 8 + (lane & 7);
    int bk = (bq & 1) * 8;

    int s = 0;
    #pragma unroll 1
    for (int kt = 0; kt < nk; kt++) {
        if (kt + 1 < nk) CP_WAIT1(); else CP_WAIT0();
        __syncthreads();

        uint32_t sa = sbase + (uint32_t)s * 20480u;
        #pragma unroll
        for (int kh = 0; kh < 2; kh++) {
            int k0 = kh * 16;
            uint32_t ah[4][4], bhf[2][4];
            #pragma unroll
            for (int mt = 0; mt < 4; mt++) {
                uint32_t addr = sa +
                    (uint32_t)((wm + mt * 16 + arow) * 40 + k0 + akoff) * 2;
                LDMX4(ah[mt], addr);
            }
            #pragma unroll
            for (int g = 0; g < 2; g++) {
                uint32_t addr = sa + 10240u +
                    (uint32_t)((wn + g * 16 + bn) * 40 + k0 + bk) * 2;
                LDMX4(bhf[g], addr);
            }
            #pragma unroll
            for (int mt = 0; mt < 4; mt++)
                #pragma unroll
                for (int nt = 0; nt < 4; nt++) {
                    int g = nt >> 1, h = (nt & 1) * 2;
                    MMAH(acc[mt][nt], ah[mt], bhf[g][h], bhf[g][h + 1]);
                }
        }

        if (kt + 2 < nk) {
            int ns = s + 2; if (ns >= 3) ns -= 3;
            STAGE_LOAD(ns, kt + 2);
        }
        s = (s + 1 == 3) ? 0 : s + 1;
    }
    #undef STAGE_LOAD

    int qrow = lane >> 2, qcol = (lane & 3) * 2;
    #pragma unroll
    for (int mt = 0; mt < 4; mt++) {
        #pragma unroll
        for (int rh = 0; rh < 2; rh++) {
            int row = m0 + wm + mt * 16 + qrow + rh * 8;
            #pragma unroll
            for (int nt = 0; nt < 4; nt++) {
                int col = n0 + wn + nt * 8 + qcol;
                float v0 = acc[mt][nt][rh * 2 + 0] + __ldg(&bias[col]);
                float v1 = acc[mt][nt][rh * 2 + 1] + __ldg(&bias[col + 1]);
                if (ACT == 1) { v0 = gelu_f(v0); v1 = gelu_f(v1); }
                size_t off = (size_t)row * N + col;
                if (RES) {
                    float2 rv = *reinterpret_cast<const float2*>(res + off);
                    v0 += rv.x; v1 += rv.y;
                }
                if (OUTMODE == 2) {
                    __half2 hh;
                    hh.x = __float2half_rn(v0);
                    hh.y = __float2half_rn(v1);
                    *reinterpret_cast<__half2*>(Chi + off) = hh;
                } else {
                    float2 o; o.x = v0; o.y = v1;
                    *reinterpret_cast<float2*>(Cf + off) = o;
                }
            }
        }
    }
}

// ---------------------------------------------------------------------------
// HMMA flash attention (causal), single fp16. CTA = (128 q-rows, head, batch),
// 8 warps; warp w owns S rows 16w..16w+15 (full 64 k-cols) -> in-warp softmax.
// Smem (halves): Qh[128*136]=17408, 2 x {Kh,Vh}[64*136 each]=17408/stage.
// ---------------------------------------------------------------------------
#define ATTN_SMEM 104448
#define QH_OFF 0
#define KV_OFF(s) (17408u + (uint32_t)(s) * 17408u)
#define VH_REL 8704

__device__ __forceinline__ void kv_load(
    uint32_t sb, uint32_t kvbase, const __half* qkv_hi,
    size_t rowbase, int tid)
{
    const __half* khi = qkv_hi + rowbase + 2048;
    const __half* vhi = qkv_hi + rowbase + 4096;
    #pragma unroll
    for (int j = 0; j < 4; j++) {
        int idx = j * 256 + tid;
        int r = idx >> 4, ch = idx & 15;
        size_t so = (size_t)r * 6144 + ch * 8;
        uint32_t doff = (uint32_t)(r * 136 + ch * 8);
        CP_ASYNC16(sb + (kvbase + doff) * 2, khi + so);
        CP_ASYNC16(sb + (kvbase + VH_REL + doff) * 2, vhi + so);
    }
}

__global__ __launch_bounds__(256) void attn_mma(
    const __half* __restrict__ qkv_hi, __half* __restrict__ oh)
{
    extern __shared__ __half smh[];
    uint32_t sb = smem_u32(smh);
    int qt = gridDim.x - 1 - blockIdx.x;          // heavy tiles first
    int hh = blockIdx.y, bb = blockIdx.z;
    int tid = threadIdx.x, lane = tid & 31, wid = tid >> 5;
    int q0 = qt * 128;
    int ktmax = 2 * qt + 2;

    size_t qrowbase = ((size_t)bb * 2048 + q0) * 6144 + hh * 128;

    #pragma unroll
    for (int j = 0; j < 8; j++) {
        int idx = j * 256 + tid;
        int r = idx >> 4, ch = idx & 15;
        size_t so = qrowbase + (size_t)r * 6144 + ch * 8;
        uint32_t doff = (uint32_t)(r * 136 + ch * 8);
        CP_ASYNC16(sb + (QH_OFF + doff) * 2, qkv_hi + so);
    }
    kv_load(sb, KV_OFF(0), qkv_hi,
            ((size_t)bb * 2048) * 6144 + hh * 128, tid);
    CP_COMMIT();

    float O[16][4];
    #pragma unroll
    for (int i = 0; i < 16; i++)
        #pragma unroll
        for (int j = 0; j < 4; j++) O[i][j] = 0.f;
    float m0 = -INFINITY, m1 = -INFINITY, l0 = 0.f, l1 = 0.f;

    int arow = lane & 15, akoff = (lane >> 4) * 8;
    int bq = lane >> 3;
    int bn = (bq >> 1) * 8 + (lane & 7);
    int bk = (bq & 1) * 8;
    const float scale = 0.08838834764831845f;

    #pragma unroll 1
    for (int kt = 0; kt < ktmax; kt++) {
        int s = kt & 1;
        if (kt + 1 < ktmax) {
            kv_load(sb, KV_OFF(s ^ 1), qkv_hi,
                    ((size_t)bb * 2048 + (kt + 1) * 64) * 6144 + hh * 128, tid);
            CP_COMMIT();
            CP_WAIT1();
        } else CP_WAIT0();
        __syncthreads();

        int k0 = kt * 64;
        uint32_t kvb = KV_OFF(s);

        float sacc[8][4];
        #pragma unroll
        for (int nt = 0; nt < 8; nt++)
            #pragma unroll
            for (int j = 0; j < 4; j++) sacc[nt][j] = 0.f;

        #pragma unroll
        for (int kc = 0; kc < 8; kc++) {
            uint32_t qaddr = sb +
                (uint32_t)((wid * 16 + arow) * 136 + kc * 16 + akoff) * 2;
            uint32_t ah[4];
            LDMX4(ah, qaddr);
            uint32_t kbh[4][4];
            #pragma unroll
            for (int g = 0; g < 4; g++) {
                uint32_t addr = sb +
                    (kvb + (uint32_t)((g * 16 + bn) * 136 + kc * 16 + bk)) * 2;
                LDMX4(kbh[g], addr);
            }
            #pragma unroll
            for (int nt = 0; nt < 8; nt++) {
                int g = nt >> 1, h = (nt & 1) * 2;
                MMAH(sacc[nt], ah, kbh[g][h], kbh[g][h + 1]);
            }
        }

        int r0 = q0 + wid * 16 + (lane >> 2);
        if (k0 + 63 > r0 - (lane >> 2)) {
            #pragma unroll
            for (int nt = 0; nt < 8; nt++)
                #pragma unroll
                for (int j = 0; j < 4; j++) {
                    float v = sacc[nt][j] * scale;
                    int col = k0 + nt * 8 + 2 * (lane & 3) + (j & 1);
                    int row = r0 + (j >> 1) * 8;
                    sacc[nt][j] = (col > row) ? -INFINITY : v;
                }
        } else {
            #pragma unroll
            for (int nt = 0; nt < 8; nt++)
                #pragma unroll
                for (int j = 0; j < 4; j++) sacc[nt][j] *= scale;
        }

        float mx0 = -INFINITY, mx1 = -INFINITY;
        #pragma unroll
        for (int nt = 0; nt < 8; nt++) {
            mx0 = fmaxf(mx0, fmaxf(sacc[nt][0], sacc[nt][1]));
            mx1 = fmaxf(mx1, fmaxf(sacc[nt][2], sacc[nt][3]));
        }
        mx0 = fmaxf(mx0, __shfl_xor_sync(0xffffffffu, mx0, 1));
        mx0 = fmaxf(mx0, __shfl_xor_sync(0xffffffffu, mx0, 2));
        mx1 = fmaxf(mx1, __shfl_xor_sync(0xffffffffu, mx1, 1));
        mx1 = fmaxf(mx1, __shfl_xor_sync(0xffffffffu, mx1, 2));
        float mn0 = fmaxf(m0, mx0), mn1 = fmaxf(m1, mx1);
        float a0 = __expf(m0 - mn0), a1 = __expf(m1 - mn1);
        m0 = mn0; m1 = mn1;
        float rs0 = 0.f, rs1 = 0.f;
        #pragma unroll
        for (int nt = 0; nt < 8; nt++) {
            float p0 = __expf(sacc[nt][0] - mn0);
            float p1 = __expf(sacc[nt][1] - mn0);
            float p2 = __expf(sacc[nt][2] - mn1);
            float p3 = __expf(sacc[nt][3] - mn1);
            sacc[nt][0] = p0; sacc[nt][1] = p1;
            sacc[nt][2] = p2; sacc[nt][3] = p3;
            rs0 += p0 + p1; rs1 += p2 + p3;
        }
        rs0 += __shfl_xor_sync(0xffffffffu, rs0, 1);
        rs0 += __shfl_xor_sync(0xffffffffu, rs0, 2);
        rs1 += __shfl_xor_sync(0xffffffffu, rs1, 1);
        rs1 += __shfl_xor_sync(0xffffffffu, rs1, 2);
        l0 = l0 * a0 + rs0;
        l1 = l1 * a1 + rs1;
        #pragma unroll
        for (int nt2 = 0; nt2 < 16; nt2++) {
            O[nt2][0] *= a0; O[nt2][1] *= a0;
            O[nt2][2] *= a1; O[nt2][3] *= a1;
        }

        uint32_t pfh[4][4];
        #pragma unroll
        for (int kc2 = 0; kc2 < 4; kc2++) {
            #pragma unroll
            for (int q = 0; q < 4; q++) {
                float v0 = sacc[2 * kc2 + (q >> 1)][(q & 1) * 2 + 0];
                float v1 = sacc[2 * kc2 + (q >> 1)][(q & 1) * 2 + 1];
                __half2 hp;
                hp.x = __float2half_rn(v0);
                hp.y = __float2half_rn(v1);
                pfh[kc2][q] = *reinterpret_cast<uint32_t*>(&hp);
            }
        }

        #pragma unroll
        for (int kc2 = 0; kc2 < 4; kc2++) {
            #pragma unroll
            for (int np = 0; np < 8; np++) {
                uint32_t vb[4];
                uint32_t addr = sb + (kvb + VH_REL +
                    (uint32_t)((kc2 * 16 + (lane & 15)) * 136 +
                               np * 16 + (lane >> 4) * 8)) * 2;
                LDMX4T(vb, addr);
                MMAH(O[2 * np],     pfh[kc2], vb[0], vb[1]);
                MMAH(O[2 * np + 1], pfh[kc2], vb[2], vb[3]);
            }
        }
        __syncthreads();
    }

    float inv0 = 1.0f / l0, inv1 = 1.0f / l1;
    size_t grow0 = (size_t)bb * 2048 + q0 + wid * 16 + (lane >> 2);
    #pragma unroll
    for (int nt2 = 0; nt2 < 16; nt2++) {
        int c = hh * 128 + nt2 * 8 + 2 * (lane & 3);
        {
            __half2 hp;
            hp.x = __float2half_rn(O[nt2][0] * inv0);
            hp.y = __float2half_rn(O[nt2][1] * inv0);
            *reinterpret_cast<__half2*>(oh + grow0 * 2048 + c) = hp;
        }
        {
            __half2 hp;
            hp.x = __float2half_rn(O[nt2][2] * inv1);
            hp.y = __float2half_rn(O[nt2][3] * inv1);
            *reinterpret_cast<__half2*>(oh + (grow0 + 8) * 2048 + c) = hp;
        }
    }
}

// ---------------------------------------------------------------------------
// launch
// ---------------------------------------------------------------------------
extern "C" void kernel_launch(void* const* d_in, const int* in_sizes, int n_in,
                              void* d_out, int out_size)
{
    const float* x     = (const float*)d_in[0];
    const float* ln1_g = (const float*)d_in[1];
    const float* ln1_b = (const float*)d_in[2];
    const float* ln2_g = (const float*)d_in[3];
    const float* ln2_b = (const float*)d_in[4];
    const float* w_qkv = (const float*)d_in[5];
    const float* b_qkv = (const float*)d_in[6];
    const float* w_ao  = (const float*)d_in[7];
    const float* b_ao  = (const float*)d_in[8];
    const float* w_ff1 = (const float*)d_in[9];
    const float* b_ff1 = (const float*)d_in[10];
    const float* w_ff2 = (const float*)d_in[11];
    const float* b_ff2 = (const float*)d_in[12];
    float* out = (float*)d_out;

    void* p;
    float* xmid;
    __half *qh, *h_hi, *at_hi, *f1_hi;
    __half *wq, *wao, *wf1, *wf2;
    cudaGetSymbolAddress(&p, g_xmid);   xmid  = (float*)p;
    cudaGetSymbolAddress(&p, g_qkv_hi); qh    = (__half*)p;
    cudaGetSymbolAddress(&p, g_h_hi);   h_hi  = (__half*)p;
    cudaGetSymbolAddress(&p, g_at_hi);  at_hi = (__half*)p;
    cudaGetSymbolAddress(&p, g_f1_hi);  f1_hi = (__half*)p;
    cudaGetSymbolAddress(&p, g_wqkv);   wq    = (__half*)p;
    cudaGetSymbolAddress(&p, g_wao);    wao   = (__half*)p;
    cudaGetSymbolAddress(&p, g_wf1);    wf1   = (__half*)p;
    cudaGetSymbolAddress(&p, g_wf2);    wf2   = (__half*)p;

    cudaFuncSetAttribute(attn_mma,
        cudaFuncAttributeMaxDynamicSharedMemorySize, ATTN_SMEM);
    cudaFuncSetAttribute(gemm_mma<0, false, 2>,
        cudaFuncAttributeMaxDynamicSharedMemorySize, GEMM_SMEM);
    cudaFuncSetAttribute(gemm_mma<0, true, 0>,
        cudaFuncAttributeMaxDynamicSharedMemorySize, GEMM_SMEM);
    cudaFuncSetAttribute(gemm_mma<1, false, 2>,
        cudaFuncAttributeMaxDynamicSharedMemorySize, GEMM_SMEM);

    // 0) fused weight transpose (all four W[K,N] -> [N,K] fp16, one launch)
    wtrans_all<<<WT_TOTAL, 256>>>(w_qkv, wq, w_ao, wao, w_ff1, wf1, w_ff2, wf2);

    // 1) LN1 -> fp16
    ln_kernel<<<GPT_BS, 256>>>(x, ln1_g, ln1_b, h_hi);
    // 2) QKV -> fp16   [4096 x 6144 x 2048]
    gemm_mma<0, false, 2><<<dim3(48, 32), 256, GEMM_SMEM>>>(
        h_hi, wq, b_qkv, nullptr, nullptr, qh,
        GPT_BS, 3 * GPT_H, GPT_H);
    // 3) HMMA flash attention -> fp16
    attn_mma<<<dim3(GPT_S / 128, 16, GPT_B), 256, ATTN_SMEM>>>(qh, at_hi);
    // 4) xmid = x + attn @ w_ao + b     [4096 x 2048 x 2048]
    gemm_mma<0, true, 0><<<dim3(16, 32), 256, GEMM_SMEM>>>(
        at_hi, wao, b_ao, x, xmid, nullptr,
        GPT_BS, GPT_H, GPT_H);
    // 5) LN2 -> fp16
    ln_kernel<<<GPT_BS, 256>>>(xmid, ln2_g, ln2_b, h_hi);
    // 6) ff1 = gelu(h @ w_ff1 + b) -> fp16   [4096 x 8192 x 2048]
    gemm_mma<1, false, 2><<<dim3(64, 32), 256, GEMM_SMEM>>>(
        h_hi, wf1, b_ff1, nullptr, nullptr, f1_hi,
        GPT_BS, 4 * GPT_H, GPT_H);
    // 7) out = xmid + ff1 @ w_ff2 + b   [4096 x 2048 x 8192]
    gemm_mma<0, true, 0><<<dim3(16, 32), 256, GEMM_SMEM>>>(
        f1_hi, wf2, b_ff2, xmid, out, nullptr,
        GPT_BS, GPT_H, 4 * GPT_H);
}